// round 3
// baseline (speedup 1.0000x reference)
#include <cuda_runtime.h>

typedef unsigned long long ull;

// Problem-fixed sizes: N=50000, E=600000, EP=200000, D=128, L=3
constexpr int NMAX = 50000;
constexpr int EMAX = 600000;

// Scratch (device globals: no runtime allocation allowed)
__device__ __align__(16) float g_b0[NMAX * 128];
__device__ __align__(16) float g_b1[NMAX * 128];
__device__ __align__(16) float g_ag[NMAX * 128];
__device__ int   g_counts[NMAX];
__device__ int   g_offsets[NMAX + 1];
__device__ int   g_cursor[NMAX];
__device__ float g_invdeg[NMAX];
__device__ int   g_csr[EMAX];
__device__ int   g_ei64;   // 1 if edge_index is int64, else int32
__device__ int   g_pi64;   // 1 if predict_edge_index is int64, else int32

// Buffer selector: 0=g_b0, 1=g_b1, 2=g_ag, anything else = external pointer
__device__ __forceinline__ const float* selbuf(int s, const float* ext) {
    if (s == 0) return g_b0;
    if (s == 1) return g_b1;
    if (s == 2) return g_ag;
    return ext;
}
__device__ __forceinline__ float* selout(int s) {
    if (s == 0) return g_b0;
    if (s == 1) return g_b1;
    return g_ag;
}

__device__ __forceinline__ int getidx(const void* p, long long pos, int is64) {
    if (is64) return (int)((const long long*)p)[pos];
    return ((const int*)p)[pos];
}

__device__ __forceinline__ ull ffma2(ull a, ull b, ull c) {
    ull d;
    asm("fma.rn.f32x2 %0, %1, %2, %3;" : "=l"(d) : "l"(a), "l"(b), "l"(c));
    return d;
}
__device__ __forceinline__ float2 unpack2(ull p) {
    float lo, hi;
    asm("mov.b64 {%0, %1}, %2;" : "=f"(lo), "=f"(hi) : "l"(p));
    return make_float2(lo, hi);
}

// ---------------------------------------------------------------------------
// Index-dtype detection: int64 small values => all odd 32-bit words are zero.
// ---------------------------------------------------------------------------
__global__ void detect64_kernel(const unsigned int* __restrict__ words, int which) {
    unsigned v = words[2 * threadIdx.x + 1];   // 256 odd words, needs >=512 words
    int all0 = __syncthreads_and(v == 0u);
    if (threadIdx.x == 0) {
        if (which == 0) g_ei64 = all0; else g_pi64 = all0;
    }
}

// ---------------------------------------------------------------------------
// CSR build (indices dtype-agnostic via g_ei64)
// ---------------------------------------------------------------------------
__global__ void zero_counts_kernel(int n) {
    int i = blockIdx.x * blockDim.x + threadIdx.x;
    if (i < n) g_counts[i] = 0;
}

__global__ void count_kernel(const void* __restrict__ ei, int E) {
    int e = blockIdx.x * blockDim.x + threadIdx.x;
    if (e < E) {
        int d = getidx(ei, (long long)E + e, g_ei64);   // dst row
        atomicAdd(&g_counts[d], 1);
    }
}

__global__ void scan_kernel(int n) {
    __shared__ int sh[1024];
    __shared__ int carry;
    if (threadIdx.x == 0) carry = 0;
    __syncthreads();
    for (int base = 0; base < n; base += 1024) {
        int i = base + (int)threadIdx.x;
        int c = (i < n) ? g_counts[i] : 0;
        sh[threadIdx.x] = c;
        __syncthreads();
        for (int off = 1; off < 1024; off <<= 1) {
            int v = (threadIdx.x >= (unsigned)off) ? sh[threadIdx.x - off] : 0;
            __syncthreads();
            sh[threadIdx.x] += v;
            __syncthreads();
        }
        if (i < n) {
            int excl = carry + sh[threadIdx.x] - c;
            g_offsets[i] = excl;
            g_cursor[i]  = excl;
            g_invdeg[i]  = 1.0f / (float)max(c, 1);
        }
        __syncthreads();
        if (threadIdx.x == 1023) carry += sh[1023];
        __syncthreads();
    }
    if (threadIdx.x == 0) g_offsets[n] = carry;
}

__global__ void fill_kernel(const void* __restrict__ ei, int E) {
    int e = blockIdx.x * blockDim.x + threadIdx.x;
    if (e < E) {
        int s = getidx(ei, e, g_ei64);
        int d = getidx(ei, (long long)E + e, g_ei64);
        int pos = atomicAdd(&g_cursor[d], 1);
        g_csr[pos] = s;
    }
}

// ---------------------------------------------------------------------------
// Mean aggregation: one warp per node, float4 over 128 dims. Output = g_ag.
// ---------------------------------------------------------------------------
__global__ void aggr_kernel(const float* __restrict__ xext, int xsel, int n) {
    int w = (blockIdx.x * blockDim.x + threadIdx.x) >> 5;
    int lane = threadIdx.x & 31;
    if (w >= n) return;
    const float* x = selbuf(xsel, xext);
    int beg = g_offsets[w];
    int end = g_offsets[w + 1];
    const float4* __restrict__ x4 = (const float4*)x;
    float4 acc = make_float4(0.f, 0.f, 0.f, 0.f);
    for (int j = beg; j < end; ++j) {
        int s = g_csr[j];
        float4 v = x4[s * 32 + lane];
        acc.x += v.x; acc.y += v.y; acc.z += v.z; acc.w += v.w;
    }
    float inv = g_invdeg[w];
    acc.x *= inv; acc.y *= inv; acc.z *= inv; acc.w *= inv;
    ((float4*)g_ag)[w * 32 + lane] = acc;
}

// ---------------------------------------------------------------------------
// Fused GEMM: C[M,128] = act( A1@W1 (+ A2@W2) (+ bias) ), K=128 per operand.
// Block = 64 rows x 128 cols, 256 threads, 4x8 per thread via fma.rn.f32x2.
// Static smem only (~33KB): W chunk [32][128] + dup-transposed A chunk.
// ---------------------------------------------------------------------------
__global__ void __launch_bounds__(256)
gemm_kernel(const float* __restrict__ Aext, int a1sel, int a2sel,
            const float* __restrict__ W1, const float* __restrict__ W2,
            const float* __restrict__ bias, int csel, int M, int doRelu) {
    __shared__ __align__(16) float  Ws[32][128];   // 16 KB
    __shared__ __align__(16) float2 As2[32][66];   // 16.9 KB (values duplicated (v,v))

    const int tid = threadIdx.x;
    const int m0 = blockIdx.x * 64;
    const int cn = (tid & 15) * 8;     // 8 output cols (4 f32x2 pairs)
    const int rm = (tid >> 4) * 4;     // 4 output rows

    ull acc[4][4];
#pragma unroll
    for (int i = 0; i < 4; i++)
#pragma unroll
        for (int j = 0; j < 4; j++) acc[i][j] = 0ULL;

    const int nops = (a2sel == -1) ? 1 : 2;

    for (int op = 0; op < nops; op++) {
        const float* A = (op == 0) ? selbuf(a1sel, Aext) : selbuf(a2sel, Aext);
        const float* W = (op == 0) ? W1 : W2;
        for (int kc = 0; kc < 128; kc += 32) {
            __syncthreads();
            for (int i = tid; i < 32 * 128; i += 256)
                (&Ws[0][0])[i] = W[kc * 128 + i];
            for (int i = tid; i < 64 * 32; i += 256) {
                int r = i >> 5;
                int k = i & 31;
                int gr = m0 + r;
                float v = (gr < M) ? A[gr * 128 + kc + k] : 0.f;
                As2[k][r] = make_float2(v, v);
            }
            __syncthreads();
#pragma unroll
            for (int k = 0; k < 32; k++) {
                ulonglong2 a01 = *(const ulonglong2*)&As2[k][rm];
                ulonglong2 a23 = *(const ulonglong2*)&As2[k][rm + 2];
                ulonglong2 w01 = *(const ulonglong2*)&Ws[k][cn];
                ulonglong2 w23 = *(const ulonglong2*)&Ws[k][cn + 4];
                ull av[4] = {a01.x, a01.y, a23.x, a23.y};
                ull wv[4] = {w01.x, w01.y, w23.x, w23.y};
#pragma unroll
                for (int i = 0; i < 4; i++)
#pragma unroll
                    for (int j = 0; j < 4; j++)
                        acc[i][j] = ffma2(av[i], wv[j], acc[i][j]);
            }
        }
    }

    float bb[8];
#pragma unroll
    for (int j = 0; j < 8; j++) bb[j] = bias ? bias[cn + j] : 0.f;

    float* C = selout(csel);
#pragma unroll
    for (int i = 0; i < 4; i++) {
        int gr = m0 + rm + i;
        if (gr < M) {
            float v[8];
#pragma unroll
            for (int jp = 0; jp < 4; jp++) {
                float2 p = unpack2(acc[i][jp]);
                float t0 = p.x + bb[2 * jp];
                float t1 = p.y + bb[2 * jp + 1];
                v[2 * jp]     = doRelu ? fmaxf(t0, 0.f) : t0;
                v[2 * jp + 1] = doRelu ? fmaxf(t1, 0.f) : t1;
            }
            *(float4*)(C + gr * 128 + cn)     = make_float4(v[0], v[1], v[2], v[3]);
            *(float4*)(C + gr * 128 + cn + 4) = make_float4(v[4], v[5], v[6], v[7]);
        }
    }
}

// ---------------------------------------------------------------------------
// Edge predict: y[e] = relu(U[i] + V[j] + qb1) . qW2 + qb2  (one warp/edge)
// ---------------------------------------------------------------------------
__global__ void predict_kernel(const void* __restrict__ pidx,
                               int usel, int vsel,
                               const float* __restrict__ qb1,
                               const float* __restrict__ qW2,
                               const float* __restrict__ qb2,
                               float* __restrict__ y, int EP) {
    int w = (blockIdx.x * blockDim.x + threadIdx.x) >> 5;
    int lane = threadIdx.x & 31;
    if (w >= EP) return;
    const float* U = selbuf(usel, nullptr);
    const float* V = selbuf(vsel, nullptr);
    int is64 = g_pi64;
    int i = getidx(pidx, w, is64);
    int j = getidx(pidx, (long long)EP + w, is64);
    float4 u = ((const float4*)U)[i * 32 + lane];
    float4 v = ((const float4*)V)[j * 32 + lane];
    float4 b = ((const float4*)qb1)[lane];
    float4 q = ((const float4*)qW2)[lane];
    float h0 = fmaxf(u.x + v.x + b.x, 0.f);
    float h1 = fmaxf(u.y + v.y + b.y, 0.f);
    float h2 = fmaxf(u.z + v.z + b.z, 0.f);
    float h3 = fmaxf(u.w + v.w + b.w, 0.f);
    float p = h0 * q.x + h1 * q.y + h2 * q.z + h3 * q.w;
#pragma unroll
    for (int o = 16; o > 0; o >>= 1) p += __shfl_xor_sync(0xFFFFFFFFu, p, o);
    if (lane == 0) y[w] = p + qb2[0];
}

// ---------------------------------------------------------------------------
// Launch: kernel launches ONLY (graph-capturable, no host device-APIs)
// ---------------------------------------------------------------------------
extern "C" void kernel_launch(void* const* d_in, const int* in_sizes, int n_in,
                              void* d_out, int out_size) {
    const float* x   = (const float*)d_in[0];
    const void*  ei  = d_in[2];
    const void*  pi  = d_in[3];
    const float* Wl  = (const float*)d_in[4];
    const float* bl  = (const float*)d_in[5];
    const float* Wr  = (const float*)d_in[6];
    // d_in[7..10]: edge-update MLP params — dead code w.r.t. the output
    const float* pW1 = (const float*)d_in[11];
    const float* pb1 = (const float*)d_in[12];
    const float* pW2 = (const float*)d_in[13];
    const float* pb2 = (const float*)d_in[14];
    const float* qW1 = (const float*)d_in[15];
    const float* qb1 = (const float*)d_in[16];
    const float* qW2 = (const float*)d_in[17];
    const float* qb2 = (const float*)d_in[18];

    const int N  = in_sizes[0] / 128;
    const int E  = in_sizes[2] / 2;
    const int EP = in_sizes[3] / 2;
    const int L  = in_sizes[4] / (128 * 128);

    // Detect index dtype (int32 vs int64) before touching indices
    detect64_kernel<<<1, 256>>>((const unsigned int*)ei, 0);
    detect64_kernel<<<1, 256>>>((const unsigned int*)pi, 1);

    // CSR build (dst is layer-invariant)
    zero_counts_kernel<<<(N + 255) / 256, 256>>>(N);
    count_kernel<<<(E + 255) / 256, 256>>>(ei, E);
    scan_kernel<<<1, 1024>>>(N);
    fill_kernel<<<(E + 255) / 256, 256>>>(ei, E);

    const int gemm_blocks = (N + 63) / 64;
    const int aggr_blocks = (N * 32 + 255) / 256;

    // GNN layers. cur: sel 3 = external x initially, then alternate b0/b1.
    int cur_sel = 3;            // external x
    int nxt_sel = 0;            // b0
    for (int l = 0; l < L; l++) {
        aggr_kernel<<<aggr_blocks, 256>>>(x, cur_sel, N);
        gemm_kernel<<<gemm_blocks, 256>>>(
            x, /*a1=*/2, /*a2=*/cur_sel,
            Wl + l * 16384, Wr + l * 16384, bl + l * 128,
            /*c=*/nxt_sel, N, 1);
        cur_sel = nxt_sel;
        nxt_sel = (cur_sel == 0) ? 1 : 0;
    }
    // Post MLP: z = relu(cur@pW1+pb1) -> ag ; xp = z@pW2+pb2 -> nxt
    gemm_kernel<<<gemm_blocks, 256>>>(nullptr, cur_sel, -1, pW1, nullptr, pb1, 2, N, 1);
    int xp_sel = nxt_sel;
    gemm_kernel<<<gemm_blocks, 256>>>(nullptr, 2, -1, pW2, nullptr, pb2, xp_sel, N, 0);

    // Predict factorization: U = xp@qW1[:128] -> other node buffer, V = xp@qW1[128:] -> ag
    int u_sel = (xp_sel == 0) ? 1 : 0;
    gemm_kernel<<<gemm_blocks, 256>>>(nullptr, xp_sel, -1, qW1,         nullptr, nullptr, u_sel, N, 0);
    gemm_kernel<<<gemm_blocks, 256>>>(nullptr, xp_sel, -1, qW1 + 16384, nullptr, nullptr, 2,     N, 0);

    predict_kernel<<<(EP * 32 + 255) / 256, 256>>>(pi, u_sel, 2, qb1, qW2, qb2,
                                                   (float*)d_out, EP);
}

// round 4
// speedup vs baseline: 1.6035x; 1.6035x over previous
#include <cuda_runtime.h>

typedef unsigned long long ull;

// Problem-fixed sizes: N=50000, E=600000, EP=200000, D=128, L=3
constexpr int NMAX = 50000;
constexpr int EMAX = 600000;

// Scratch (device globals: no runtime allocation allowed)
__device__ __align__(16) float g_b0[NMAX * 128];
__device__ __align__(16) float g_b1[NMAX * 128];
__device__ __align__(16) float g_ag[NMAX * 128];
__device__ int   g_counts[NMAX];
__device__ int   g_offsets[NMAX];
__device__ int   g_cursor[NMAX];
__device__ float g_invdeg[NMAX];
__device__ int   g_csr[EMAX];
__device__ int   g_total;
__device__ int   g_ei64;   // 1 if edge_index is int64, else int32
__device__ int   g_pi64;   // 1 if predict_edge_index is int64, else int32

// Buffer selector: 0=g_b0, 1=g_b1, 2=g_ag, anything else = external pointer
__device__ __forceinline__ const float* selbuf(int s, const float* ext) {
    if (s == 0) return g_b0;
    if (s == 1) return g_b1;
    if (s == 2) return g_ag;
    return ext;
}
__device__ __forceinline__ float* selout(int s) {
    if (s == 0) return g_b0;
    if (s == 1) return g_b1;
    return g_ag;
}

__device__ __forceinline__ int getidx(const void* p, long long pos, int is64) {
    if (is64) return (int)((const long long*)p)[pos];
    return ((const int*)p)[pos];
}

__device__ __forceinline__ ull ffma2(ull a, ull b, ull c) {
    ull d;
    asm("fma.rn.f32x2 %0, %1, %2, %3;" : "=l"(d) : "l"(a), "l"(b), "l"(c));
    return d;
}
__device__ __forceinline__ ull pack2(float lo, float hi) {
    ull p;
    asm("mov.b64 %0, {%1, %2};" : "=l"(p) : "f"(lo), "f"(hi));
    return p;
}
__device__ __forceinline__ float2 unpack2(ull p) {
    float lo, hi;
    asm("mov.b64 {%0, %1}, %2;" : "=f"(lo), "=f"(hi) : "l"(p));
    return make_float2(lo, hi);
}

// ---------------------------------------------------------------------------
// Index-dtype detection: int64 small values => all odd 32-bit words are zero.
// ---------------------------------------------------------------------------
__global__ void detect64_kernel(const unsigned int* __restrict__ words, int which) {
    unsigned v = words[2 * threadIdx.x + 1];
    int all0 = __syncthreads_and(v == 0u);
    if (threadIdx.x == 0) {
        if (which == 0) g_ei64 = all0; else g_pi64 = all0;
    }
}

// ---------------------------------------------------------------------------
// CSR build (unordered disjoint segments; no global scan needed)
// ---------------------------------------------------------------------------
__global__ void zero_counts_kernel(int n) {
    int i = blockIdx.x * blockDim.x + threadIdx.x;
    if (i < n) g_counts[i] = 0;
    if (i == 0) g_total = 0;
}

__global__ void count_kernel(const void* __restrict__ ei, int E) {
    int e = blockIdx.x * blockDim.x + threadIdx.x;
    if (e < E) {
        int d = getidx(ei, (long long)E + e, g_ei64);
        atomicAdd(&g_counts[d], 1);
    }
}

// Parallel segment assignment: block-local scan + one atomicAdd per block.
__global__ void segment_kernel(int n) {
    __shared__ int wsum[8];
    __shared__ int blockbase;
    int i = blockIdx.x * 256 + threadIdx.x;
    int lane = threadIdx.x & 31;
    int wid  = threadIdx.x >> 5;
    int c = (i < n) ? g_counts[i] : 0;
    // warp inclusive scan
    int s = c;
#pragma unroll
    for (int off = 1; off < 32; off <<= 1) {
        int v = __shfl_up_sync(0xFFFFFFFFu, s, off);
        if (lane >= off) s += v;
    }
    if (lane == 31) wsum[wid] = s;
    __syncthreads();
    if (wid == 0) {
        int v = (lane < 8) ? wsum[lane] : 0;
#pragma unroll
        for (int off = 1; off < 8; off <<= 1) {
            int t = __shfl_up_sync(0xFFFFFFFFu, v, off);
            if (lane >= off) v += t;
        }
        if (lane < 8) wsum[lane] = v;          // inclusive warp-sums
        int total = __shfl_sync(0xFFFFFFFFu, v, 7);
        if (lane == 0) blockbase = atomicAdd(&g_total, total);
    }
    __syncthreads();
    if (i < n) {
        int excl = blockbase + (wid > 0 ? wsum[wid - 1] : 0) + s - c;
        g_offsets[i] = excl;
        g_cursor[i]  = excl;
        g_invdeg[i]  = 1.0f / (float)max(c, 1);
    }
}

__global__ void fill_kernel(const void* __restrict__ ei, int E) {
    int e = blockIdx.x * blockDim.x + threadIdx.x;
    if (e < E) {
        int s = getidx(ei, e, g_ei64);
        int d = getidx(ei, (long long)E + e, g_ei64);
        int pos = atomicAdd(&g_cursor[d], 1);
        g_csr[pos] = s;
    }
}

// ---------------------------------------------------------------------------
// Mean aggregation: one warp per node, float4 over 128 dims. Output = g_ag.
// ---------------------------------------------------------------------------
__global__ void aggr_kernel(const float* __restrict__ xext, int xsel, int n) {
    int w = (blockIdx.x * blockDim.x + threadIdx.x) >> 5;
    int lane = threadIdx.x & 31;
    if (w >= n) return;
    const float* x = selbuf(xsel, xext);
    int beg = g_offsets[w];
    int cnt = g_counts[w];
    const float4* __restrict__ x4 = (const float4*)x;
    float4 acc = make_float4(0.f, 0.f, 0.f, 0.f);
    for (int j = beg; j < beg + cnt; ++j) {
        int s = g_csr[j];
        float4 v = x4[s * 32 + lane];
        acc.x += v.x; acc.y += v.y; acc.z += v.z; acc.w += v.w;
    }
    float inv = g_invdeg[w];
    acc.x *= inv; acc.y *= inv; acc.z *= inv; acc.w *= inv;
    ((float4*)g_ag)[w * 32 + lane] = acc;
}

// ---------------------------------------------------------------------------
// Fused GEMM: C[M,128] = act( A1@W1 (+ A2@W2) (+ bias) ), K=128 per operand.
// Block tile 128x128, 256 threads, thread tile 8 rows (4+4 split) x 8 cols.
// fma.rn.f32x2 throughout; conflict-free LDS in the mainloop.
// ---------------------------------------------------------------------------
__global__ void __launch_bounds__(256, 2)
gemm_kernel(const float* __restrict__ Aext, int a1sel, int a2sel,
            const float* __restrict__ W1, const float* __restrict__ W2,
            const float* __restrict__ bias, int csel, int M, int doRelu) {
    __shared__ __align__(16) float Ws[32][128];   // 16 KB
    __shared__ __align__(16) float As[32][132];   // 16.5 KB (pad 132)

    const int tid = threadIdx.x;
    const int m0 = blockIdx.x * 128;
    const int cn = (tid >> 4) * 8;     // 0..120 (8 cols = 4 f32x2 pairs)
    const int r0 = (tid & 15) * 4;     // rows r0..r0+3 and r0+64..r0+67

    ull acc[8][4];
#pragma unroll
    for (int i = 0; i < 8; i++)
#pragma unroll
        for (int j = 0; j < 4; j++) acc[i][j] = 0ULL;

    const int nops = (a2sel == -1) ? 1 : 2;

    for (int op = 0; op < nops; op++) {
        const float* A = (op == 0) ? selbuf(a1sel, Aext) : selbuf(a2sel, Aext);
        const float* W = (op == 0) ? W1 : W2;
        for (int kc = 0; kc < 128; kc += 32) {
            __syncthreads();
            // W chunk: contiguous 4096 floats, float4 copy
            {
                const float4* Wg = (const float4*)(W + kc * 128);
                float4* Wsm = (float4*)&Ws[0][0];
                for (int i = tid; i < 1024; i += 256) Wsm[i] = Wg[i];
            }
            // A chunk: coalesced float4 reads along k, transposed scalar stores
            for (int i = tid; i < 1024; i += 256) {
                int r  = i >> 3;          // 0..127
                int kq = (i & 7) * 4;     // 0,4,...,28
                int gr = m0 + r;
                float4 v = make_float4(0.f, 0.f, 0.f, 0.f);
                if (gr < M) v = *(const float4*)(A + gr * 128 + kc + kq);
                As[kq + 0][r] = v.x;
                As[kq + 1][r] = v.y;
                As[kq + 2][r] = v.z;
                As[kq + 3][r] = v.w;
            }
            __syncthreads();
#pragma unroll
            for (int k = 0; k < 32; k++) {
                float4 a0 = *(const float4*)&As[k][r0];
                float4 a1 = *(const float4*)&As[k][r0 + 64];
                ulonglong2 w01 = *(const ulonglong2*)&Ws[k][cn];
                ulonglong2 w23 = *(const ulonglong2*)&Ws[k][cn + 4];
                ull wv[4] = {w01.x, w01.y, w23.x, w23.y};
                float av[8] = {a0.x, a0.y, a0.z, a0.w, a1.x, a1.y, a1.z, a1.w};
#pragma unroll
                for (int i = 0; i < 8; i++) {
                    ull ad = pack2(av[i], av[i]);
#pragma unroll
                    for (int j = 0; j < 4; j++)
                        acc[i][j] = ffma2(ad, wv[j], acc[i][j]);
                }
            }
        }
    }

    float bb[8];
#pragma unroll
    for (int j = 0; j < 8; j++) bb[j] = bias ? bias[cn + j] : 0.f;

    float* C = selout(csel);
#pragma unroll
    for (int g = 0; g < 2; g++) {
#pragma unroll
        for (int i = 0; i < 4; i++) {
            int gr = m0 + r0 + g * 64 + i;
            if (gr < M) {
                int ai = g * 4 + i;
                float v[8];
#pragma unroll
                for (int jp = 0; jp < 4; jp++) {
                    float2 p = unpack2(acc[ai][jp]);
                    float t0 = p.x + bb[2 * jp];
                    float t1 = p.y + bb[2 * jp + 1];
                    v[2 * jp]     = doRelu ? fmaxf(t0, 0.f) : t0;
                    v[2 * jp + 1] = doRelu ? fmaxf(t1, 0.f) : t1;
                }
                *(float4*)(C + gr * 128 + cn)     = make_float4(v[0], v[1], v[2], v[3]);
                *(float4*)(C + gr * 128 + cn + 4) = make_float4(v[4], v[5], v[6], v[7]);
            }
        }
    }
}

// ---------------------------------------------------------------------------
// Edge predict: y[e] = relu(U[i] + V[j] + qb1) . qW2 + qb2  (one warp/edge)
// ---------------------------------------------------------------------------
__global__ void predict_kernel(const void* __restrict__ pidx,
                               int usel, int vsel,
                               const float* __restrict__ qb1,
                               const float* __restrict__ qW2,
                               const float* __restrict__ qb2,
                               float* __restrict__ y, int EP) {
    int w = (blockIdx.x * blockDim.x + threadIdx.x) >> 5;
    int lane = threadIdx.x & 31;
    if (w >= EP) return;
    const float* U = selbuf(usel, nullptr);
    const float* V = selbuf(vsel, nullptr);
    int is64 = g_pi64;
    int i = getidx(pidx, w, is64);
    int j = getidx(pidx, (long long)EP + w, is64);
    float4 u = ((const float4*)U)[i * 32 + lane];
    float4 v = ((const float4*)V)[j * 32 + lane];
    float4 b = ((const float4*)qb1)[lane];
    float4 q = ((const float4*)qW2)[lane];
    float h0 = fmaxf(u.x + v.x + b.x, 0.f);
    float h1 = fmaxf(u.y + v.y + b.y, 0.f);
    float h2 = fmaxf(u.z + v.z + b.z, 0.f);
    float h3 = fmaxf(u.w + v.w + b.w, 0.f);
    float p = h0 * q.x + h1 * q.y + h2 * q.z + h3 * q.w;
#pragma unroll
    for (int o = 16; o > 0; o >>= 1) p += __shfl_xor_sync(0xFFFFFFFFu, p, o);
    if (lane == 0) y[w] = p + qb2[0];
}

// ---------------------------------------------------------------------------
// Launch: kernel launches ONLY (graph-capturable, no host device-APIs)
// ---------------------------------------------------------------------------
extern "C" void kernel_launch(void* const* d_in, const int* in_sizes, int n_in,
                              void* d_out, int out_size) {
    const float* x   = (const float*)d_in[0];
    const void*  ei  = d_in[2];
    const void*  pi  = d_in[3];
    const float* Wl  = (const float*)d_in[4];
    const float* bl  = (const float*)d_in[5];
    const float* Wr  = (const float*)d_in[6];
    // d_in[7..10]: edge-update MLP params — dead code w.r.t. the output
    const float* pW1 = (const float*)d_in[11];
    const float* pb1 = (const float*)d_in[12];
    const float* pW2 = (const float*)d_in[13];
    const float* pb2 = (const float*)d_in[14];
    const float* qW1 = (const float*)d_in[15];
    const float* qb1 = (const float*)d_in[16];
    const float* qW2 = (const float*)d_in[17];
    const float* qb2 = (const float*)d_in[18];

    const int N  = in_sizes[0] / 128;
    const int E  = in_sizes[2] / 2;
    const int EP = in_sizes[3] / 2;
    const int L  = in_sizes[4] / (128 * 128);

    // Detect index dtype (int32 vs int64) before touching indices
    detect64_kernel<<<1, 256>>>((const unsigned int*)ei, 0);
    detect64_kernel<<<1, 256>>>((const unsigned int*)pi, 1);

    // CSR build (dst is layer-invariant; segments unordered but disjoint)
    zero_counts_kernel<<<(N + 255) / 256, 256>>>(N);
    count_kernel<<<(E + 255) / 256, 256>>>(ei, E);
    segment_kernel<<<(N + 255) / 256, 256>>>(N);
    fill_kernel<<<(E + 255) / 256, 256>>>(ei, E);

    const int gemm_blocks = (N + 127) / 128;
    const int aggr_blocks = (N * 32 + 255) / 256;

    // GNN layers. cur: sel 3 = external x initially, then alternate b0/b1.
    int cur_sel = 3;            // external x
    int nxt_sel = 0;            // b0
    for (int l = 0; l < L; l++) {
        aggr_kernel<<<aggr_blocks, 256>>>(x, cur_sel, N);
        gemm_kernel<<<gemm_blocks, 256>>>(
            x, /*a1=*/2, /*a2=*/cur_sel,
            Wl + l * 16384, Wr + l * 16384, bl + l * 128,
            /*c=*/nxt_sel, N, 1);
        cur_sel = nxt_sel;
        nxt_sel = (cur_sel == 0) ? 1 : 0;
    }
    // Post MLP: z = relu(cur@pW1+pb1) -> ag ; xp = z@pW2+pb2 -> nxt
    gemm_kernel<<<gemm_blocks, 256>>>(nullptr, cur_sel, -1, pW1, nullptr, pb1, 2, N, 1);
    int xp_sel = nxt_sel;
    gemm_kernel<<<gemm_blocks, 256>>>(nullptr, 2, -1, pW2, nullptr, pb2, xp_sel, N, 0);

    // Predict factorization: U = xp@qW1[:128] -> other node buffer, V = xp@qW1[128:] -> ag
    int u_sel = (xp_sel == 0) ? 1 : 0;
    gemm_kernel<<<gemm_blocks, 256>>>(nullptr, xp_sel, -1, qW1,         nullptr, nullptr, u_sel, N, 0);
    gemm_kernel<<<gemm_blocks, 256>>>(nullptr, xp_sel, -1, qW1 + 16384, nullptr, nullptr, 2,     N, 0);

    predict_kernel<<<(EP * 32 + 255) / 256, 256>>>(pi, u_sel, 2, qb1, qW2, qb2,
                                                   (float*)d_out, EP);
}

// round 5
// speedup vs baseline: 1.8135x; 1.1310x over previous
#include <cuda_runtime.h>

typedef unsigned long long ull;

// Problem-fixed sizes: N=50000, E=600000, EP=200000, D=128, L=3
constexpr int NMAX = 50000;
constexpr int EMAX = 600000;

// Scratch (device globals: no runtime allocation allowed)
__device__ __align__(16) float g_b0[NMAX * 128];
__device__ __align__(16) float g_b1[NMAX * 128];
__device__ __align__(16) float g_ag[NMAX * 128];
__device__ int   g_counts[NMAX];
__device__ int   g_offsets[NMAX];
__device__ int   g_cursor[NMAX];
__device__ float g_invdeg[NMAX];
__device__ int   g_csr[EMAX];
__device__ int   g_total;
__device__ int   g_ei64;   // 1 if edge_index is int64, else int32
__device__ int   g_pi64;   // 1 if predict_edge_index is int64, else int32

// Buffer selector: 0=g_b0, 1=g_b1, 2=g_ag, anything else = external pointer
__device__ __forceinline__ const float* selbuf(int s, const float* ext) {
    if (s == 0) return g_b0;
    if (s == 1) return g_b1;
    if (s == 2) return g_ag;
    return ext;
}
__device__ __forceinline__ float* selout(int s) {
    if (s == 0) return g_b0;
    if (s == 1) return g_b1;
    return g_ag;
}

__device__ __forceinline__ int getidx(const void* p, long long pos, int is64) {
    if (is64) return (int)((const long long*)p)[pos];
    return ((const int*)p)[pos];
}

__device__ __forceinline__ ull ffma2(ull a, ull b, ull c) {
    ull d;
    asm("fma.rn.f32x2 %0, %1, %2, %3;" : "=l"(d) : "l"(a), "l"(b), "l"(c));
    return d;
}
__device__ __forceinline__ ull pack2(float lo, float hi) {
    ull p;
    asm("mov.b64 %0, {%1, %2};" : "=l"(p) : "f"(lo), "f"(hi));
    return p;
}
__device__ __forceinline__ float2 unpack2(ull p) {
    float lo, hi;
    asm("mov.b64 {%0, %1}, %2;" : "=f"(lo), "=f"(hi) : "l"(p));
    return make_float2(lo, hi);
}

// ---------------------------------------------------------------------------
// Init: zero counts everywhere; block 0 additionally detects index dtypes
// (int64 small values => all odd 32-bit words are zero) and resets g_total.
// ---------------------------------------------------------------------------
__global__ void init_kernel(const unsigned int* __restrict__ eiw,
                            const unsigned int* __restrict__ piw, int n) {
    int i = blockIdx.x * blockDim.x + threadIdx.x;
    if (i < n) g_counts[i] = 0;
    if (blockIdx.x == 0) {
        unsigned ve = eiw[2 * threadIdx.x + 1];
        unsigned vp = piw[2 * threadIdx.x + 1];
        int e0 = __syncthreads_and(ve == 0u);
        int p0 = __syncthreads_and(vp == 0u);
        if (threadIdx.x == 0) {
            g_ei64 = e0;
            g_pi64 = p0;
            g_total = 0;
        }
    }
}

// ---------------------------------------------------------------------------
// CSR build (unordered disjoint segments; no global scan needed)
// ---------------------------------------------------------------------------
__global__ void count_kernel(const void* __restrict__ ei, int E) {
    int e = blockIdx.x * blockDim.x + threadIdx.x;
    if (e < E) {
        int d = getidx(ei, (long long)E + e, g_ei64);
        atomicAdd(&g_counts[d], 1);
    }
}

// Parallel segment assignment: block-local scan + one atomicAdd per block.
__global__ void segment_kernel(int n) {
    __shared__ int wsum[8];
    __shared__ int blockbase;
    int i = blockIdx.x * 256 + threadIdx.x;
    int lane = threadIdx.x & 31;
    int wid  = threadIdx.x >> 5;
    int c = (i < n) ? g_counts[i] : 0;
    int s = c;
#pragma unroll
    for (int off = 1; off < 32; off <<= 1) {
        int v = __shfl_up_sync(0xFFFFFFFFu, s, off);
        if (lane >= off) s += v;
    }
    if (lane == 31) wsum[wid] = s;
    __syncthreads();
    if (wid == 0) {
        int v = (lane < 8) ? wsum[lane] : 0;
#pragma unroll
        for (int off = 1; off < 8; off <<= 1) {
            int t = __shfl_up_sync(0xFFFFFFFFu, v, off);
            if (lane >= off) v += t;
        }
        if (lane < 8) wsum[lane] = v;
        int total = __shfl_sync(0xFFFFFFFFu, v, 7);
        if (lane == 0) blockbase = atomicAdd(&g_total, total);
    }
    __syncthreads();
    if (i < n) {
        int excl = blockbase + (wid > 0 ? wsum[wid - 1] : 0) + s - c;
        g_offsets[i] = excl;
        g_cursor[i]  = excl;
        g_invdeg[i]  = 1.0f / (float)max(c, 1);
    }
}

__global__ void fill_kernel(const void* __restrict__ ei, int E) {
    int e = blockIdx.x * blockDim.x + threadIdx.x;
    if (e < E) {
        int s = getidx(ei, e, g_ei64);
        int d = getidx(ei, (long long)E + e, g_ei64);
        int pos = atomicAdd(&g_cursor[d], 1);
        g_csr[pos] = s;
    }
}

// ---------------------------------------------------------------------------
// Mean aggregation: one warp per node, float4 over 128 dims. Output = g_ag.
// ---------------------------------------------------------------------------
__global__ void aggr_kernel(const float* __restrict__ xext, int xsel, int n) {
    int w = (blockIdx.x * blockDim.x + threadIdx.x) >> 5;
    int lane = threadIdx.x & 31;
    if (w >= n) return;
    const float* x = selbuf(xsel, xext);
    int beg = g_offsets[w];
    int cnt = g_counts[w];
    const float4* __restrict__ x4 = (const float4*)x;
    float4 acc = make_float4(0.f, 0.f, 0.f, 0.f);
    for (int j = beg; j < beg + cnt; ++j) {
        int s = g_csr[j];
        float4 v = x4[s * 32 + lane];
        acc.x += v.x; acc.y += v.y; acc.z += v.z; acc.w += v.w;
    }
    float inv = g_invdeg[w];
    acc.x *= inv; acc.y *= inv; acc.z *= inv; acc.w *= inv;
    ((float4*)g_ag)[w * 32 + lane] = acc;
}

// ---------------------------------------------------------------------------
// Fused GEMM: C[M,128] = act( A1@W1 (+ A2@W2) (+ bias) ), K=128 per operand.
// Block tile 128x128, 256 threads, thread tile 8 rows (4+4 split) x 8 cols.
// fma.rn.f32x2 + double-buffered 16-k chunks (gmem->reg prefetch).
// blockIdx.y==1 (optional): use W1b/cselb instead (batched second GEMM).
// ---------------------------------------------------------------------------
__global__ void __launch_bounds__(256, 2)
gemm_kernel(const float* __restrict__ Aext, int a1sel, int a2sel,
            const float* __restrict__ W1, const float* __restrict__ W2,
            const float* __restrict__ bias, int csel, int M, int doRelu,
            const float* __restrict__ W1b, int cselb) {
    __shared__ __align__(16) float Ws[2][16][128];   // 16 KB
    __shared__ __align__(16) float As[2][16][132];   // 16.9 KB

    if (blockIdx.y == 1) { W1 = W1b; csel = cselb; }

    const int tid = threadIdx.x;
    const int m0 = blockIdx.x * 128;
    const int cn = (tid >> 4) * 8;     // 0..120 (8 cols = 4 f32x2 pairs)
    const int r0 = (tid & 15) * 4;     // rows r0..r0+3 and r0+64..r0+67

    const float* A1 = selbuf(a1sel, Aext);
    const float* A2 = (a2sel == -1) ? nullptr : selbuf(a2sel, Aext);
    const int nch = (a2sel == -1) ? 8 : 16;   // 16-k chunks, flat across ops

    // Per-thread staging indices
    // W chunk: 2048 floats = 512 float4; thread does i=tid, tid+256
    // A chunk: 512 float4 (r = i>>2, kq = (i&3)*4)
    const int aw_r0 = tid >> 2;            // row for A stage 0 (0..63)
    const int aw_k0 = (tid & 3) * 4;
    const int aw_r1 = (tid + 256) >> 2;    // row for A stage 1 (64..127)
    const int aw_k1 = aw_k0;

    float4 wst[2], ast[2];

    // Prefetch chunk 0
    {
        const float* W = W1;
        const float* A = A1;
        wst[0] = ((const float4*)W)[tid];
        wst[1] = ((const float4*)W)[tid + 256];
        int gr0 = m0 + aw_r0, gr1 = m0 + aw_r1;
        ast[0] = (gr0 < M) ? *(const float4*)(A + gr0 * 128 + aw_k0)
                           : make_float4(0.f, 0.f, 0.f, 0.f);
        ast[1] = (gr1 < M) ? *(const float4*)(A + gr1 * 128 + aw_k1)
                           : make_float4(0.f, 0.f, 0.f, 0.f);
    }
    // Store chunk 0 into buffer 0
    {
        ((float4*)&Ws[0][0][0])[tid]       = wst[0];
        ((float4*)&Ws[0][0][0])[tid + 256] = wst[1];
        As[0][aw_k0 + 0][aw_r0] = ast[0].x;
        As[0][aw_k0 + 1][aw_r0] = ast[0].y;
        As[0][aw_k0 + 2][aw_r0] = ast[0].z;
        As[0][aw_k0 + 3][aw_r0] = ast[0].w;
        As[0][aw_k1 + 0][aw_r1] = ast[1].x;
        As[0][aw_k1 + 1][aw_r1] = ast[1].y;
        As[0][aw_k1 + 2][aw_r1] = ast[1].z;
        As[0][aw_k1 + 3][aw_r1] = ast[1].w;
    }
    __syncthreads();

    ull acc[8][4];
#pragma unroll
    for (int i = 0; i < 8; i++)
#pragma unroll
        for (int j = 0; j < 4; j++) acc[i][j] = 0ULL;

    for (int c = 0; c < nch; c++) {
        const int cb = c & 1;
        // Prefetch chunk c+1 into registers
        if (c + 1 < nch) {
            int cc = c + 1;
            int op = cc >> 3;
            int kc = (cc & 7) * 16;
            const float* W = (op == 0) ? W1 : W2;
            const float* A = (op == 0) ? A1 : A2;
            wst[0] = ((const float4*)(W + kc * 128))[tid];
            wst[1] = ((const float4*)(W + kc * 128))[tid + 256];
            int gr0 = m0 + aw_r0, gr1 = m0 + aw_r1;
            ast[0] = (gr0 < M) ? *(const float4*)(A + gr0 * 128 + kc + aw_k0)
                               : make_float4(0.f, 0.f, 0.f, 0.f);
            ast[1] = (gr1 < M) ? *(const float4*)(A + gr1 * 128 + kc + aw_k1)
                               : make_float4(0.f, 0.f, 0.f, 0.f);
        }
        // Compute from buffer cb
#pragma unroll
        for (int k = 0; k < 16; k++) {
            float4 a0 = *(const float4*)&As[cb][k][r0];
            float4 a1 = *(const float4*)&As[cb][k][r0 + 64];
            ulonglong2 w01 = *(const ulonglong2*)&Ws[cb][k][cn];
            ulonglong2 w23 = *(const ulonglong2*)&Ws[cb][k][cn + 4];
            ull wv[4] = {w01.x, w01.y, w23.x, w23.y};
            float av[8] = {a0.x, a0.y, a0.z, a0.w, a1.x, a1.y, a1.z, a1.w};
#pragma unroll
            for (int i = 0; i < 8; i++) {
                ull ad = pack2(av[i], av[i]);
#pragma unroll
                for (int j = 0; j < 4; j++)
                    acc[i][j] = ffma2(ad, wv[j], acc[i][j]);
            }
        }
        // Store prefetched chunk into the other buffer
        if (c + 1 < nch) {
            const int nb = cb ^ 1;
            ((float4*)&Ws[nb][0][0])[tid]       = wst[0];
            ((float4*)&Ws[nb][0][0])[tid + 256] = wst[1];
            As[nb][aw_k0 + 0][aw_r0] = ast[0].x;
            As[nb][aw_k0 + 1][aw_r0] = ast[0].y;
            As[nb][aw_k0 + 2][aw_r0] = ast[0].z;
            As[nb][aw_k0 + 3][aw_r0] = ast[0].w;
            As[nb][aw_k1 + 0][aw_r1] = ast[1].x;
            As[nb][aw_k1 + 1][aw_r1] = ast[1].y;
            As[nb][aw_k1 + 2][aw_r1] = ast[1].z;
            As[nb][aw_k1 + 3][aw_r1] = ast[1].w;
        }
        __syncthreads();
    }

    float bb[8];
#pragma unroll
    for (int j = 0; j < 8; j++) bb[j] = bias ? bias[cn + j] : 0.f;

    float* C = selout(csel);
#pragma unroll
    for (int g = 0; g < 2; g++) {
#pragma unroll
        for (int i = 0; i < 4; i++) {
            int gr = m0 + r0 + g * 64 + i;
            if (gr < M) {
                int ai = g * 4 + i;
                float v[8];
#pragma unroll
                for (int jp = 0; jp < 4; jp++) {
                    float2 p = unpack2(acc[ai][jp]);
                    float t0 = p.x + bb[2 * jp];
                    float t1 = p.y + bb[2 * jp + 1];
                    v[2 * jp]     = doRelu ? fmaxf(t0, 0.f) : t0;
                    v[2 * jp + 1] = doRelu ? fmaxf(t1, 0.f) : t1;
                }
                *(float4*)(C + gr * 128 + cn)     = make_float4(v[0], v[1], v[2], v[3]);
                *(float4*)(C + gr * 128 + cn + 4) = make_float4(v[4], v[5], v[6], v[7]);
            }
        }
    }
}

// ---------------------------------------------------------------------------
// Edge predict: y[e] = relu(U[i] + V[j] + qb1) . qW2 + qb2  (one warp/edge)
// ---------------------------------------------------------------------------
__global__ void predict_kernel(const void* __restrict__ pidx,
                               int usel, int vsel,
                               const float* __restrict__ qb1,
                               const float* __restrict__ qW2,
                               const float* __restrict__ qb2,
                               float* __restrict__ y, int EP) {
    int w = (blockIdx.x * blockDim.x + threadIdx.x) >> 5;
    int lane = threadIdx.x & 31;
    if (w >= EP) return;
    const float* U = selbuf(usel, nullptr);
    const float* V = selbuf(vsel, nullptr);
    int is64 = g_pi64;
    int i = getidx(pidx, w, is64);
    int j = getidx(pidx, (long long)EP + w, is64);
    float4 u = ((const float4*)U)[i * 32 + lane];
    float4 v = ((const float4*)V)[j * 32 + lane];
    float4 b = ((const float4*)qb1)[lane];
    float4 q = ((const float4*)qW2)[lane];
    float h0 = fmaxf(u.x + v.x + b.x, 0.f);
    float h1 = fmaxf(u.y + v.y + b.y, 0.f);
    float h2 = fmaxf(u.z + v.z + b.z, 0.f);
    float h3 = fmaxf(u.w + v.w + b.w, 0.f);
    float p = h0 * q.x + h1 * q.y + h2 * q.z + h3 * q.w;
#pragma unroll
    for (int o = 16; o > 0; o >>= 1) p += __shfl_xor_sync(0xFFFFFFFFu, p, o);
    if (lane == 0) y[w] = p + qb2[0];
}

// ---------------------------------------------------------------------------
// Launch: kernel launches ONLY (graph-capturable, no host device-APIs)
// ---------------------------------------------------------------------------
extern "C" void kernel_launch(void* const* d_in, const int* in_sizes, int n_in,
                              void* d_out, int out_size) {
    const float* x   = (const float*)d_in[0];
    const void*  ei  = d_in[2];
    const void*  pi  = d_in[3];
    const float* Wl  = (const float*)d_in[4];
    const float* bl  = (const float*)d_in[5];
    const float* Wr  = (const float*)d_in[6];
    // d_in[7..10]: edge-update MLP params — dead code w.r.t. the output
    const float* pW1 = (const float*)d_in[11];
    const float* pb1 = (const float*)d_in[12];
    const float* pW2 = (const float*)d_in[13];
    const float* pb2 = (const float*)d_in[14];
    const float* qW1 = (const float*)d_in[15];
    const float* qb1 = (const float*)d_in[16];
    const float* qW2 = (const float*)d_in[17];
    const float* qb2 = (const float*)d_in[18];

    const int N  = in_sizes[0] / 128;
    const int E  = in_sizes[2] / 2;
    const int EP = in_sizes[3] / 2;
    const int L  = in_sizes[4] / (128 * 128);

    // 1: init (zero counts + dtype detect + total reset)
    init_kernel<<<(N + 255) / 256, 256>>>((const unsigned int*)ei,
                                          (const unsigned int*)pi, N);
    // 2-4: CSR build (dst is layer-invariant; segments unordered but disjoint)
    count_kernel<<<(E + 255) / 256, 256>>>(ei, E);
    segment_kernel<<<(N + 255) / 256, 256>>>(N);
    fill_kernel<<<(E + 255) / 256, 256>>>(ei, E);

    const int gemm_blocks = (N + 127) / 128;
    const int aggr_blocks = (N * 32 + 255) / 256;

    // GNN layers. cur: sel 3 = external x initially, then alternate b0/b1.
    int cur_sel = 3;            // external x
    int nxt_sel = 0;            // b0
    for (int l = 0; l < L; l++) {
        aggr_kernel<<<aggr_blocks, 256>>>(x, cur_sel, N);
        gemm_kernel<<<gemm_blocks, 256>>>(
            x, /*a1=*/2, /*a2=*/cur_sel,
            Wl + l * 16384, Wr + l * 16384, bl + l * 128,
            /*c=*/nxt_sel, N, 1, nullptr, 0);
        cur_sel = nxt_sel;
        nxt_sel = (cur_sel == 0) ? 1 : 0;
    }
    // Post MLP: z = relu(cur@pW1+pb1) -> ag ; xp = z@pW2+pb2 -> nxt
    gemm_kernel<<<gemm_blocks, 256>>>(nullptr, cur_sel, -1, pW1, nullptr, pb1,
                                      2, N, 1, nullptr, 0);
    int xp_sel = nxt_sel;
    gemm_kernel<<<gemm_blocks, 256>>>(nullptr, 2, -1, pW2, nullptr, pb2,
                                      xp_sel, N, 0, nullptr, 0);

    // Predict factorization, batched in one launch:
    //  y-block 0: U = xp@qW1[:128] -> u_sel ; y-block 1: V = xp@qW1[128:] -> ag
    int u_sel = (xp_sel == 0) ? 1 : 0;
    dim3 grid_uv(gemm_blocks, 2);
    gemm_kernel<<<grid_uv, 256>>>(nullptr, xp_sel, -1, qW1, nullptr, nullptr,
                                  u_sel, N, 0, qW1 + 16384, 2);

    predict_kernel<<<(EP * 32 + 255) / 256, 256>>>(pi, u_sel, 2, qb1, qW2, qb2,
                                                   (float*)d_out, EP);
}

// round 7
// speedup vs baseline: 2.1409x; 1.1805x over previous
#include <cuda_runtime.h>
#include <cuda_bf16.h>
#include <cstdint>

typedef __nv_bfloat16 bf16;

// Problem-fixed sizes: N=50000, E=600000, EP=200000, D=128, L=3
constexpr int NMAX = 50000;
constexpr int EMAX = 600000;

// fp32 scratch (U, V for predict)
__device__ __align__(16) float g_b0[NMAX * 128];
__device__ __align__(16) float g_b1[NMAX * 128];
// bf16 hi/lo node-feature pairs: 0=x, 1=p0, 2=p1, 3=ag
__device__ __align__(16) bf16 g_xh[NMAX * 128];
__device__ __align__(16) bf16 g_xl[NMAX * 128];
__device__ __align__(16) bf16 g_p0h[NMAX * 128];
__device__ __align__(16) bf16 g_p0l[NMAX * 128];
__device__ __align__(16) bf16 g_p1h[NMAX * 128];
__device__ __align__(16) bf16 g_p1l[NMAX * 128];
__device__ __align__(16) bf16 g_agh[NMAX * 128];
__device__ __align__(16) bf16 g_agl[NMAX * 128];
// Packed weights: 40 chunks x 4096 bf16 ([k=32][n=128] plain layout)
__device__ __align__(16) bf16 g_wh[40 * 4096];
__device__ __align__(16) bf16 g_wl[40 * 4096];
// CSR
__device__ int   g_counts[NMAX];
__device__ int   g_offsets[NMAX];
__device__ int   g_cursor[NMAX];
__device__ float g_invdeg[NMAX];
__device__ int   g_csr[EMAX];
__device__ int   g_total;
__device__ int   g_ei64;
__device__ int   g_pi64;

__device__ __forceinline__ const bf16* pair_h(int s) {
    if (s == 0) return g_xh;
    if (s == 1) return g_p0h;
    if (s == 2) return g_p1h;
    return g_agh;
}
__device__ __forceinline__ const bf16* pair_l(int s) {
    if (s == 0) return g_xl;
    if (s == 1) return g_p0l;
    if (s == 2) return g_p1l;
    return g_agl;
}

__device__ __forceinline__ int getidx(const void* p, long long pos, int is64) {
    if (is64) return (int)((const long long*)p)[pos];
    return ((const int*)p)[pos];
}

__device__ __forceinline__ uint32_t smem_u32(const void* p) {
    uint32_t a;
    asm("{ .reg .u64 t; cvta.to.shared.u64 t, %1; cvt.u32.u64 %0, t; }" : "=r"(a) : "l"(p));
    return a;
}
__device__ __forceinline__ void ldmx4(uint32_t* r, uint32_t addr) {
    asm volatile("ldmatrix.sync.aligned.m8n8.x4.shared.b16 {%0,%1,%2,%3}, [%4];"
                 : "=r"(r[0]), "=r"(r[1]), "=r"(r[2]), "=r"(r[3]) : "r"(addr));
}
__device__ __forceinline__ void ldmx4t(uint32_t* r, uint32_t addr) {
    asm volatile("ldmatrix.sync.aligned.m8n8.x4.trans.shared.b16 {%0,%1,%2,%3}, [%4];"
                 : "=r"(r[0]), "=r"(r[1]), "=r"(r[2]), "=r"(r[3]) : "r"(addr));
}
__device__ __forceinline__ void mma16816(float* c, const uint32_t* a, const uint32_t* b) {
    asm volatile(
        "mma.sync.aligned.m16n8k16.row.col.f32.bf16.bf16.f32 "
        "{%0,%1,%2,%3}, {%4,%5,%6,%7}, {%8,%9}, {%0,%1,%2,%3};"
        : "+f"(c[0]), "+f"(c[1]), "+f"(c[2]), "+f"(c[3])
        : "r"(a[0]), "r"(a[1]), "r"(a[2]), "r"(a[3]), "r"(b[0]), "r"(b[1]));
}

// ---------------------------------------------------------------------------
// Weight prep: pack + transpose + bf16-split into plain [k=32][n=128] chunks.
// cg layout: g0:0-7 g1:8-15 g2:16-23 (layers, K=256) g3:24-27 g4:28-31
//            g5:32-35 g6:36-39 (K=128 each)
// ---------------------------------------------------------------------------
__global__ void prep_w_kernel(const float* __restrict__ Wl, const float* __restrict__ Wr,
                              const float* __restrict__ pW1, const float* __restrict__ pW2,
                              const float* __restrict__ qW1) {
    int t = blockIdx.x * blockDim.x + threadIdx.x;
    if (t >= 40 * 4096) return;
    int cg = t >> 12;
    int within = t & 4095;
    int kl = within >> 7;      // 0..31
    int n  = within & 127;
    int g, c;
    if (cg < 24) { g = cg >> 3; c = cg & 7; }
    else { g = 3 + ((cg - 24) >> 2); c = (cg - 24) & 3; }
    int kk = c * 32 + kl;
    float v;
    if (g < 3) v = (kk < 128) ? Wl[g * 16384 + kk * 128 + n]
                              : Wr[g * 16384 + (kk - 128) * 128 + n];
    else if (g == 3) v = pW1[kk * 128 + n];
    else if (g == 4) v = pW2[kk * 128 + n];
    else if (g == 5) v = qW1[kk * 128 + n];
    else             v = qW1[(128 + kk) * 128 + n];
    bf16 hi = __float2bfloat16(v);
    bf16 lo = __float2bfloat16(v - __bfloat162float(hi));
    g_wh[cg * 4096 + kl * 128 + n] = hi;
    g_wl[cg * 4096 + kl * 128 + n] = lo;
}

// ---------------------------------------------------------------------------
// Convert x (fp32) -> bf16 hi/lo pair (sel 0)
// ---------------------------------------------------------------------------
__global__ void convert_x_kernel(const float* __restrict__ x, int n32) {
    int i = blockIdx.x * blockDim.x + threadIdx.x;
    if (i >= n32) return;
    float4 v = ((const float4*)x)[i];
    bf16 h0 = __float2bfloat16(v.x), h1 = __float2bfloat16(v.y);
    bf16 h2 = __float2bfloat16(v.z), h3 = __float2bfloat16(v.w);
    bf16 l0 = __float2bfloat16(v.x - __bfloat162float(h0));
    bf16 l1 = __float2bfloat16(v.y - __bfloat162float(h1));
    bf16 l2 = __float2bfloat16(v.z - __bfloat162float(h2));
    bf16 l3 = __float2bfloat16(v.w - __bfloat162float(h3));
    __nv_bfloat162 hA = __halves2bfloat162(h0, h1), hB = __halves2bfloat162(h2, h3);
    __nv_bfloat162 lA = __halves2bfloat162(l0, l1), lB = __halves2bfloat162(l2, l3);
    ((uint2*)g_xh)[i] = make_uint2(*(uint32_t*)&hA, *(uint32_t*)&hB);
    ((uint2*)g_xl)[i] = make_uint2(*(uint32_t*)&lA, *(uint32_t*)&lB);
}

// ---------------------------------------------------------------------------
// Init / CSR build
// ---------------------------------------------------------------------------
__global__ void init_kernel(const unsigned int* __restrict__ eiw,
                            const unsigned int* __restrict__ piw, int n) {
    int i = blockIdx.x * blockDim.x + threadIdx.x;
    if (i < n) g_counts[i] = 0;
    if (blockIdx.x == 0) {
        unsigned ve = eiw[2 * threadIdx.x + 1];
        unsigned vp = piw[2 * threadIdx.x + 1];
        int e0 = __syncthreads_and(ve == 0u);
        int p0 = __syncthreads_and(vp == 0u);
        if (threadIdx.x == 0) { g_ei64 = e0; g_pi64 = p0; g_total = 0; }
    }
}

__global__ void count_kernel(const void* __restrict__ ei, int E) {
    int e = blockIdx.x * blockDim.x + threadIdx.x;
    if (e < E) atomicAdd(&g_counts[getidx(ei, (long long)E + e, g_ei64)], 1);
}

__global__ void segment_kernel(int n) {
    __shared__ int wsum[8];
    __shared__ int blockbase;
    int i = blockIdx.x * 256 + threadIdx.x;
    int lane = threadIdx.x & 31;
    int wid  = threadIdx.x >> 5;
    int c = (i < n) ? g_counts[i] : 0;
    int s = c;
#pragma unroll
    for (int off = 1; off < 32; off <<= 1) {
        int v = __shfl_up_sync(0xFFFFFFFFu, s, off);
        if (lane >= off) s += v;
    }
    if (lane == 31) wsum[wid] = s;
    __syncthreads();
    if (wid == 0) {
        int v = (lane < 8) ? wsum[lane] : 0;
#pragma unroll
        for (int off = 1; off < 8; off <<= 1) {
            int t2 = __shfl_up_sync(0xFFFFFFFFu, v, off);
            if (lane >= off) v += t2;
        }
        if (lane < 8) wsum[lane] = v;
        int total = __shfl_sync(0xFFFFFFFFu, v, 7);
        if (lane == 0) blockbase = atomicAdd(&g_total, total);
    }
    __syncthreads();
    if (i < n) {
        int excl = blockbase + (wid > 0 ? wsum[wid - 1] : 0) + s - c;
        g_offsets[i] = excl;
        g_cursor[i]  = excl;
        g_invdeg[i]  = 1.0f / (float)max(c, 1);
    }
}

__global__ void fill_kernel(const void* __restrict__ ei, int E) {
    int e = blockIdx.x * blockDim.x + threadIdx.x;
    if (e < E) {
        int s = getidx(ei, e, g_ei64);
        int d = getidx(ei, (long long)E + e, g_ei64);
        g_csr[atomicAdd(&g_cursor[d], 1)] = s;
    }
}

// ---------------------------------------------------------------------------
// Mean aggregation over bf16 pairs -> ag bf16 pair. One warp/node.
// ---------------------------------------------------------------------------
__global__ void aggr_kernel(int xsel, int n) {
    int w = (blockIdx.x * blockDim.x + threadIdx.x) >> 5;
    int lane = threadIdx.x & 31;
    if (w >= n) return;
    const bf16* xh = pair_h(xsel);
    const bf16* xl = pair_l(xsel);
    int beg = g_offsets[w];
    int cnt = g_counts[w];
    float a0 = 0.f, a1 = 0.f, a2 = 0.f, a3 = 0.f;
    for (int j = beg; j < beg + cnt; ++j) {
        int s = g_csr[j];
        uint2 uh = *(const uint2*)(xh + s * 128 + lane * 4);
        uint2 ul = *(const uint2*)(xl + s * 128 + lane * 4);
        __nv_bfloat162 h01 = *(__nv_bfloat162*)&uh.x;
        __nv_bfloat162 h23 = *(__nv_bfloat162*)&uh.y;
        __nv_bfloat162 l01 = *(__nv_bfloat162*)&ul.x;
        __nv_bfloat162 l23 = *(__nv_bfloat162*)&ul.y;
        a0 += __low2float(h01)  + __low2float(l01);
        a1 += __high2float(h01) + __high2float(l01);
        a2 += __low2float(h23)  + __low2float(l23);
        a3 += __high2float(h23) + __high2float(l23);
    }
    float inv = g_invdeg[w];
    a0 *= inv; a1 *= inv; a2 *= inv; a3 *= inv;
    bf16 h0 = __float2bfloat16(a0), h1 = __float2bfloat16(a1);
    bf16 h2 = __float2bfloat16(a2), h3 = __float2bfloat16(a3);
    bf16 l0 = __float2bfloat16(a0 - __bfloat162float(h0));
    bf16 l1 = __float2bfloat16(a1 - __bfloat162float(h1));
    bf16 l2 = __float2bfloat16(a2 - __bfloat162float(h2));
    bf16 l3 = __float2bfloat16(a3 - __bfloat162float(h3));
    __nv_bfloat162 hA = __halves2bfloat162(h0, h1), hB = __halves2bfloat162(h2, h3);
    __nv_bfloat162 lA = __halves2bfloat162(l0, l1), lB = __halves2bfloat162(l2, l3);
    *(uint2*)(g_agh + w * 128 + lane * 4) = make_uint2(*(uint32_t*)&hA, *(uint32_t*)&hB);
    *(uint2*)(g_agl + w * 128 + lane * 4) = make_uint2(*(uint32_t*)&lA, *(uint32_t*)&lB);
}

// ---------------------------------------------------------------------------
// Tensor-core GEMM via mma.sync (bf16 3-term split, fp32 accum).
// C[M,128] = act( A@Wg (+bias) ). Dual: K=256 (chunks 0-3 a1sel, 4-7 a2sel).
// Block 128x128, 8 warps (4x2), warp tile 32x64. K chunk = 32 in smem.
// blockIdx.y selects (wbase0,outsel0)/(wbase1,outsel1). outmode 0: bf16 pair
// to outsel; 1: fp32 to g_b0/g_b1.
// ---------------------------------------------------------------------------
constexpr int A_ST = 40;    // bf16 stride (pad 32->40): +20 banks/row
constexpr int W_ST = 136;   // bf16 stride (pad 128->136): +4 banks/row

__global__ void __launch_bounds__(256)
gemm_mma(int a1sel, int a2sel, int wbase0, int wbase1,
         const float* __restrict__ bias, int relu, int outmode,
         int outsel0, int outsel1, int M) {
    __shared__ __align__(16) bf16 sAh[128 * A_ST];
    __shared__ __align__(16) bf16 sAl[128 * A_ST];
    __shared__ __align__(16) bf16 sWh[32 * W_ST];
    __shared__ __align__(16) bf16 sWl[32 * W_ST];

    const int wbase  = (blockIdx.y == 0) ? wbase0 : wbase1;
    const int outsel = (blockIdx.y == 0) ? outsel0 : outsel1;

    const int tid = threadIdx.x;
    const int wid = tid >> 5;
    const int lane = tid & 31;
    const int wr = wid >> 1;          // warp row 0..3 (32 rows each)
    const int wc = wid & 1;           // warp col 0..1 (64 cols each)
    const int m0 = blockIdx.x * 128;
    const int lrow = lane & 15;
    const int lhalf = lane >> 4;

    float acc[2][8][4];
#pragma unroll
    for (int i = 0; i < 2; i++)
#pragma unroll
        for (int j = 0; j < 8; j++)
#pragma unroll
            for (int k = 0; k < 4; k++) acc[i][j][k] = 0.f;

    const uint32_t aBaseH = smem_u32(sAh);
    const uint32_t aBaseL = smem_u32(sAl);
    const uint32_t wBaseH = smem_u32(sWh);
    const uint32_t wBaseL = smem_u32(sWl);

    const int nch = (a2sel < 0) ? 4 : 8;

    for (int c = 0; c < nch; c++) {
        const int half = (nch == 8 && c >= 4) ? 1 : 0;
        const int psel = half ? a2sel : a1sel;
        const bf16* Ah = pair_h(psel);
        const bf16* Al = pair_l(psel);
        const int kbase = (c & 3) * 32;
        const bf16* wh = g_wh + (size_t)(wbase + c) * 4096;
        const bf16* wl = g_wl + (size_t)(wbase + c) * 4096;

        // Stage A chunk [128][32] (512 uint4) and W chunk [32][128] (512 uint4)
#pragma unroll
        for (int it = 0; it < 2; it++) {
            int i = tid + it * 256;
            {   // A
                int r = i >> 2, q = i & 3;
                int gr = m0 + r;
                uint4 vh = make_uint4(0, 0, 0, 0), vl = make_uint4(0, 0, 0, 0);
                if (gr < M) {
                    vh = *(const uint4*)(Ah + (size_t)gr * 128 + kbase + q * 8);
                    vl = *(const uint4*)(Al + (size_t)gr * 128 + kbase + q * 8);
                }
                *(uint4*)(sAh + r * A_ST + q * 8) = vh;
                *(uint4*)(sAl + r * A_ST + q * 8) = vl;
            }
            {   // W
                int r = i >> 4, q = i & 15;
                *(uint4*)(sWh + r * W_ST + q * 8) = ((const uint4*)wh)[i];
                *(uint4*)(sWl + r * W_ST + q * 8) = ((const uint4*)wl)[i];
            }
        }
        __syncthreads();

#pragma unroll
        for (int ks = 0; ks < 2; ks++) {
            uint32_t aH[2][4], aL[2][4];
#pragma unroll
            for (int mt = 0; mt < 2; mt++) {
                uint32_t off = (uint32_t)(((32 * wr + 16 * mt + lrow) * A_ST +
                                           ks * 16 + 8 * lhalf) * 2);
                ldmx4(aH[mt], aBaseH + off);
                ldmx4(aL[mt], aBaseL + off);
            }
#pragma unroll
            for (int ng = 0; ng < 4; ng++) {
                uint32_t bH[4], bL[4];
                uint32_t off = (uint32_t)(((ks * 16 + lrow) * W_ST +
                                           64 * wc + 16 * ng + 8 * lhalf) * 2);
                ldmx4t(bH, wBaseH + off);
                ldmx4t(bL, wBaseL + off);
#pragma unroll
                for (int mt = 0; mt < 2; mt++) {
                    mma16816(acc[mt][2 * ng],     aH[mt], bH);
                    mma16816(acc[mt][2 * ng],     aH[mt], bL);
                    mma16816(acc[mt][2 * ng],     aL[mt], bH);
                    mma16816(acc[mt][2 * ng + 1], aH[mt], bH + 2);
                    mma16816(acc[mt][2 * ng + 1], aH[mt], bL + 2);
                    mma16816(acc[mt][2 * ng + 1], aL[mt], bH + 2);
                }
            }
        }
        __syncthreads();
    }

    // Epilogue: c-frag (mt,nt): rows m0+32*wr+16*mt+(lane>>2)[+8],
    // cols 64*wc+8*nt+2*(lane&3)+{0,1}
    float* Cf = (outmode == 1) ? ((outsel == 0) ? g_b0 : g_b1) : nullptr;
    bf16* oh = (outmode == 0) ? (bf16*)pair_h(outsel) : nullptr;
    bf16* ol = (outmode == 0) ? (bf16*)pair_l(outsel) : nullptr;

#pragma unroll
    for (int mt = 0; mt < 2; mt++) {
#pragma unroll
        for (int nt = 0; nt < 8; nt++) {
            int col = 64 * wc + 8 * nt + 2 * (lane & 3);
            float bb0 = bias ? bias[col] : 0.f;
            float bb1 = bias ? bias[col + 1] : 0.f;
#pragma unroll
            for (int h = 0; h < 2; h++) {
                int r = m0 + 32 * wr + 16 * mt + (lane >> 2) + 8 * h;
                if (r < M) {
                    float v0 = acc[mt][nt][2 * h]     + bb0;
                    float v1 = acc[mt][nt][2 * h + 1] + bb1;
                    if (relu) { v0 = fmaxf(v0, 0.f); v1 = fmaxf(v1, 0.f); }
                    if (outmode == 1) {
                        *(float2*)(Cf + (size_t)r * 128 + col) = make_float2(v0, v1);
                    } else {
                        bf16 h0 = __float2bfloat16(v0);
                        bf16 h1 = __float2bfloat16(v1);
                        bf16 l0 = __float2bfloat16(v0 - __bfloat162float(h0));
                        bf16 l1 = __float2bfloat16(v1 - __bfloat162float(h1));
                        __nv_bfloat162 hp = __halves2bfloat162(h0, h1);
                        __nv_bfloat162 lp = __halves2bfloat162(l0, l1);
                        *(uint32_t*)(oh + (size_t)r * 128 + col) = *(uint32_t*)&hp;
                        *(uint32_t*)(ol + (size_t)r * 128 + col) = *(uint32_t*)&lp;
                    }
                }
            }
        }
    }
}

// ---------------------------------------------------------------------------
// Edge predict: y[e] = relu(U[i] + V[j] + qb1) . qW2 + qb2  (one warp/edge)
// ---------------------------------------------------------------------------
__global__ void predict_kernel(const void* __restrict__ pidx,
                               const float* __restrict__ qb1,
                               const float* __restrict__ qW2,
                               const float* __restrict__ qb2,
                               float* __restrict__ y, int EP) {
    int w = (blockIdx.x * blockDim.x + threadIdx.x) >> 5;
    int lane = threadIdx.x & 31;
    if (w >= EP) return;
    int is64 = g_pi64;
    int i = getidx(pidx, w, is64);
    int j = getidx(pidx, (long long)EP + w, is64);
    float4 u = ((const float4*)g_b0)[i * 32 + lane];
    float4 v = ((const float4*)g_b1)[j * 32 + lane];
    float4 b = ((const float4*)qb1)[lane];
    float4 q = ((const float4*)qW2)[lane];
    float h0 = fmaxf(u.x + v.x + b.x, 0.f);
    float h1 = fmaxf(u.y + v.y + b.y, 0.f);
    float h2 = fmaxf(u.z + v.z + b.z, 0.f);
    float h3 = fmaxf(u.w + v.w + b.w, 0.f);
    float p = h0 * q.x + h1 * q.y + h2 * q.z + h3 * q.w;
#pragma unroll
    for (int o = 16; o > 0; o >>= 1) p += __shfl_xor_sync(0xFFFFFFFFu, p, o);
    if (lane == 0) y[w] = p + qb2[0];
}

// ---------------------------------------------------------------------------
// Launch
// ---------------------------------------------------------------------------
extern "C" void kernel_launch(void* const* d_in, const int* in_sizes, int n_in,
                              void* d_out, int out_size) {
    const float* x   = (const float*)d_in[0];
    const void*  ei  = d_in[2];
    const void*  pi  = d_in[3];
    const float* Wl  = (const float*)d_in[4];
    const float* bl  = (const float*)d_in[5];
    const float* Wr  = (const float*)d_in[6];
    // d_in[7..10]: edge-update MLP params — dead code w.r.t. the output
    const float* pW1 = (const float*)d_in[11];
    const float* pb1 = (const float*)d_in[12];
    const float* pW2 = (const float*)d_in[13];
    const float* pb2 = (const float*)d_in[14];
    const float* qW1 = (const float*)d_in[15];
    const float* qb1 = (const float*)d_in[16];
    const float* qW2 = (const float*)d_in[17];
    const float* qb2 = (const float*)d_in[18];

    const int N  = in_sizes[0] / 128;
    const int E  = in_sizes[2] / 2;
    const int EP = in_sizes[3] / 2;
    const int L  = in_sizes[4] / (128 * 128);

    // Weight pack + x conversion (independent of CSR)
    prep_w_kernel<<<(40 * 4096 + 255) / 256, 256>>>(Wl, Wr, pW1, pW2, qW1);
    convert_x_kernel<<<(N * 32 + 255) / 256, 256>>>(x, N * 32);

    // CSR build
    init_kernel<<<(N + 255) / 256, 256>>>((const unsigned int*)ei,
                                          (const unsigned int*)pi, N);
    count_kernel<<<(E + 255) / 256, 256>>>(ei, E);
    segment_kernel<<<(N + 255) / 256, 256>>>(N);
    fill_kernel<<<(E + 255) / 256, 256>>>(ei, E);

    const int gemm_blocks = (N + 127) / 128;
    const int aggr_blocks = (N * 32 + 255) / 256;

    // GNN layers: cur pair sel 0(x) -> 1 -> 2 -> 1
    int cur = 0;
    for (int l = 0; l < L; l++) {
        int nxt = (l == 0) ? 1 : (l == 1) ? 2 : 1;
        aggr_kernel<<<aggr_blocks, 256>>>(cur, N);
        gemm_mma<<<dim3(gemm_blocks, 1), 256>>>(
            3, cur, l * 8, 0, bl + l * 128, 1, 0, nxt, 0, N);
        cur = nxt;
    }
    // cur = 1. Post MLP: g3: p0 -> p1 (relu); g4: p1 -> p0 (no relu)
    gemm_mma<<<dim3(gemm_blocks, 1), 256>>>(1, -1, 24, 0, pb1, 1, 0, 2, 0, N);
    gemm_mma<<<dim3(gemm_blocks, 1), 256>>>(2, -1, 28, 0, pb2, 0, 0, 1, 0, N);
    // U/V batched: y=0 -> wbase 32 -> g_b0 ; y=1 -> wbase 36 -> g_b1 (fp32)
    gemm_mma<<<dim3(gemm_blocks, 2), 256>>>(1, -1, 32, 36, nullptr, 0, 1, 0, 1, N);

    predict_kernel<<<(EP * 32 + 255) / 256, 256>>>(pi, qb1, qW2, qb2, (float*)d_out, EP);
}

// round 8
// speedup vs baseline: 2.3478x; 1.0966x over previous
#include <cuda_runtime.h>
#include <cuda_bf16.h>
#include <cstdint>

typedef __nv_bfloat16 bf16;

// Problem-fixed sizes: N=50000, E=600000, EP=200000, D=128, L=3
constexpr int NMAX = 50000;
constexpr int EMAX = 600000;

// fp32 scratch (U, V for predict)
__device__ __align__(16) float g_b0[NMAX * 128];
__device__ __align__(16) float g_b1[NMAX * 128];
// bf16 hi/lo node-feature pairs: 0=x, 1=p0, 2=p1, 3=ag
__device__ __align__(16) bf16 g_xh[NMAX * 128];
__device__ __align__(16) bf16 g_xl[NMAX * 128];
__device__ __align__(16) bf16 g_p0h[NMAX * 128];
__device__ __align__(16) bf16 g_p0l[NMAX * 128];
__device__ __align__(16) bf16 g_p1h[NMAX * 128];
__device__ __align__(16) bf16 g_p1l[NMAX * 128];
__device__ __align__(16) bf16 g_agh[NMAX * 128];
__device__ __align__(16) bf16 g_agl[NMAX * 128];
// Packed weights: 40 chunks x 4096 bf16 ([k=32][n=128] plain layout)
__device__ __align__(16) bf16 g_wh[40 * 4096];
__device__ __align__(16) bf16 g_wl[40 * 4096];
// CSR
__device__ int   g_counts[NMAX];
__device__ int   g_offsets[NMAX];
__device__ int   g_cursor[NMAX];
__device__ float g_invdeg[NMAX];
__device__ int   g_csr[EMAX];
__device__ int   g_total;
__device__ int   g_ei64;
__device__ int   g_pi64;

__device__ __forceinline__ const bf16* pair_h(int s) {
    if (s == 0) return g_xh;
    if (s == 1) return g_p0h;
    if (s == 2) return g_p1h;
    return g_agh;
}
__device__ __forceinline__ const bf16* pair_l(int s) {
    if (s == 0) return g_xl;
    if (s == 1) return g_p0l;
    if (s == 2) return g_p1l;
    return g_agl;
}

__device__ __forceinline__ int getidx(const void* p, long long pos, int is64) {
    if (is64) return (int)((const long long*)p)[pos];
    return ((const int*)p)[pos];
}

__device__ __forceinline__ uint32_t smem_u32(const void* p) {
    uint32_t a;
    asm("{ .reg .u64 t; cvta.to.shared.u64 t, %1; cvt.u32.u64 %0, t; }" : "=r"(a) : "l"(p));
    return a;
}
__device__ __forceinline__ void ldmx4(uint32_t* r, uint32_t addr) {
    asm volatile("ldmatrix.sync.aligned.m8n8.x4.shared.b16 {%0,%1,%2,%3}, [%4];"
                 : "=r"(r[0]), "=r"(r[1]), "=r"(r[2]), "=r"(r[3]) : "r"(addr));
}
__device__ __forceinline__ void ldmx4t(uint32_t* r, uint32_t addr) {
    asm volatile("ldmatrix.sync.aligned.m8n8.x4.trans.shared.b16 {%0,%1,%2,%3}, [%4];"
                 : "=r"(r[0]), "=r"(r[1]), "=r"(r[2]), "=r"(r[3]) : "r"(addr));
}
__device__ __forceinline__ void mma16816(float* c, const uint32_t* a, const uint32_t* b) {
    asm volatile(
        "mma.sync.aligned.m16n8k16.row.col.f32.bf16.bf16.f32 "
        "{%0,%1,%2,%3}, {%4,%5,%6,%7}, {%8,%9}, {%0,%1,%2,%3};"
        : "+f"(c[0]), "+f"(c[1]), "+f"(c[2]), "+f"(c[3])
        : "r"(a[0]), "r"(a[1]), "r"(a[2]), "r"(a[3]), "r"(b[0]), "r"(b[1]));
}
__device__ __forceinline__ void cpasync16(uint32_t dst, const void* src, int srcsize) {
    asm volatile("cp.async.cg.shared.global [%0], [%1], 16, %2;"
                 :: "r"(dst), "l"(src), "r"(srcsize) : "memory");
}
#define CP_COMMIT() asm volatile("cp.async.commit_group;" ::: "memory")
#define CP_WAIT1()  asm volatile("cp.async.wait_group 1;" ::: "memory")
#define CP_WAIT0()  asm volatile("cp.async.wait_group 0;" ::: "memory")

// ---------------------------------------------------------------------------
// Weight prep: pack + transpose + bf16-split into plain [k=32][n=128] chunks.
// cg layout: g0:0-7 g1:8-15 g2:16-23 (layers, K=256) g3:24-27 g4:28-31
//            g5:32-35 g6:36-39 (K=128 each)
// ---------------------------------------------------------------------------
__global__ void prep_w_kernel(const float* __restrict__ Wl, const float* __restrict__ Wr,
                              const float* __restrict__ pW1, const float* __restrict__ pW2,
                              const float* __restrict__ qW1) {
    int t = blockIdx.x * blockDim.x + threadIdx.x;
    if (t >= 40 * 4096) return;
    int cg = t >> 12;
    int within = t & 4095;
    int kl = within >> 7;      // 0..31
    int n  = within & 127;
    int g, c;
    if (cg < 24) { g = cg >> 3; c = cg & 7; }
    else { g = 3 + ((cg - 24) >> 2); c = (cg - 24) & 3; }
    int kk = c * 32 + kl;
    float v;
    if (g < 3) v = (kk < 128) ? Wl[g * 16384 + kk * 128 + n]
                              : Wr[g * 16384 + (kk - 128) * 128 + n];
    else if (g == 3) v = pW1[kk * 128 + n];
    else if (g == 4) v = pW2[kk * 128 + n];
    else if (g == 5) v = qW1[kk * 128 + n];
    else             v = qW1[(128 + kk) * 128 + n];
    bf16 hi = __float2bfloat16(v);
    bf16 lo = __float2bfloat16(v - __bfloat162float(hi));
    g_wh[cg * 4096 + kl * 128 + n] = hi;
    g_wl[cg * 4096 + kl * 128 + n] = lo;
}

// ---------------------------------------------------------------------------
// Convert x (fp32) -> bf16 hi/lo pair (sel 0)
// ---------------------------------------------------------------------------
__global__ void convert_x_kernel(const float* __restrict__ x, int n32) {
    int i = blockIdx.x * blockDim.x + threadIdx.x;
    if (i >= n32) return;
    float4 v = ((const float4*)x)[i];
    bf16 h0 = __float2bfloat16(v.x), h1 = __float2bfloat16(v.y);
    bf16 h2 = __float2bfloat16(v.z), h3 = __float2bfloat16(v.w);
    bf16 l0 = __float2bfloat16(v.x - __bfloat162float(h0));
    bf16 l1 = __float2bfloat16(v.y - __bfloat162float(h1));
    bf16 l2 = __float2bfloat16(v.z - __bfloat162float(h2));
    bf16 l3 = __float2bfloat16(v.w - __bfloat162float(h3));
    __nv_bfloat162 hA = __halves2bfloat162(h0, h1), hB = __halves2bfloat162(h2, h3);
    __nv_bfloat162 lA = __halves2bfloat162(l0, l1), lB = __halves2bfloat162(l2, l3);
    ((uint2*)g_xh)[i] = make_uint2(*(uint32_t*)&hA, *(uint32_t*)&hB);
    ((uint2*)g_xl)[i] = make_uint2(*(uint32_t*)&lA, *(uint32_t*)&lB);
}

// ---------------------------------------------------------------------------
// Init / CSR build
// ---------------------------------------------------------------------------
__global__ void init_kernel(const unsigned int* __restrict__ eiw,
                            const unsigned int* __restrict__ piw, int n) {
    int i = blockIdx.x * blockDim.x + threadIdx.x;
    if (i < n) g_counts[i] = 0;
    if (blockIdx.x == 0) {
        unsigned ve = eiw[2 * threadIdx.x + 1];
        unsigned vp = piw[2 * threadIdx.x + 1];
        int e0 = __syncthreads_and(ve == 0u);
        int p0 = __syncthreads_and(vp == 0u);
        if (threadIdx.x == 0) { g_ei64 = e0; g_pi64 = p0; g_total = 0; }
    }
}

__global__ void count_kernel(const void* __restrict__ ei, int E) {
    int e = blockIdx.x * blockDim.x + threadIdx.x;
    if (e < E) atomicAdd(&g_counts[getidx(ei, (long long)E + e, g_ei64)], 1);
}

__global__ void segment_kernel(int n) {
    __shared__ int wsum[8];
    __shared__ int blockbase;
    int i = blockIdx.x * 256 + threadIdx.x;
    int lane = threadIdx.x & 31;
    int wid  = threadIdx.x >> 5;
    int c = (i < n) ? g_counts[i] : 0;
    int s = c;
#pragma unroll
    for (int off = 1; off < 32; off <<= 1) {
        int v = __shfl_up_sync(0xFFFFFFFFu, s, off);
        if (lane >= off) s += v;
    }
    if (lane == 31) wsum[wid] = s;
    __syncthreads();
    if (wid == 0) {
        int v = (lane < 8) ? wsum[lane] : 0;
#pragma unroll
        for (int off = 1; off < 8; off <<= 1) {
            int t2 = __shfl_up_sync(0xFFFFFFFFu, v, off);
            if (lane >= off) v += t2;
        }
        if (lane < 8) wsum[lane] = v;
        int total = __shfl_sync(0xFFFFFFFFu, v, 7);
        if (lane == 0) blockbase = atomicAdd(&g_total, total);
    }
    __syncthreads();
    if (i < n) {
        int excl = blockbase + (wid > 0 ? wsum[wid - 1] : 0) + s - c;
        g_offsets[i] = excl;
        g_cursor[i]  = excl;
        g_invdeg[i]  = 1.0f / (float)max(c, 1);
    }
}

__global__ void fill_kernel(const void* __restrict__ ei, int E) {
    int e = blockIdx.x * blockDim.x + threadIdx.x;
    if (e < E) {
        int s = getidx(ei, e, g_ei64);
        int d = getidx(ei, (long long)E + e, g_ei64);
        g_csr[atomicAdd(&g_cursor[d], 1)] = s;
    }
}

// ---------------------------------------------------------------------------
// Mean aggregation over bf16 pairs -> ag bf16 pair. One warp/node.
// ---------------------------------------------------------------------------
__global__ void aggr_kernel(int xsel, int n) {
    int w = (blockIdx.x * blockDim.x + threadIdx.x) >> 5;
    int lane = threadIdx.x & 31;
    if (w >= n) return;
    const bf16* xh = pair_h(xsel);
    const bf16* xl = pair_l(xsel);
    int beg = g_offsets[w];
    int cnt = g_counts[w];
    float a0 = 0.f, a1 = 0.f, a2 = 0.f, a3 = 0.f;
    for (int j = beg; j < beg + cnt; ++j) {
        int s = g_csr[j];
        uint2 uh = *(const uint2*)(xh + s * 128 + lane * 4);
        uint2 ul = *(const uint2*)(xl + s * 128 + lane * 4);
        __nv_bfloat162 h01 = *(__nv_bfloat162*)&uh.x;
        __nv_bfloat162 h23 = *(__nv_bfloat162*)&uh.y;
        __nv_bfloat162 l01 = *(__nv_bfloat162*)&ul.x;
        __nv_bfloat162 l23 = *(__nv_bfloat162*)&ul.y;
        a0 += __low2float(h01)  + __low2float(l01);
        a1 += __high2float(h01) + __high2float(l01);
        a2 += __low2float(h23)  + __low2float(l23);
        a3 += __high2float(h23) + __high2float(l23);
    }
    float inv = g_invdeg[w];
    a0 *= inv; a1 *= inv; a2 *= inv; a3 *= inv;
    bf16 h0 = __float2bfloat16(a0), h1 = __float2bfloat16(a1);
    bf16 h2 = __float2bfloat16(a2), h3 = __float2bfloat16(a3);
    bf16 l0 = __float2bfloat16(a0 - __bfloat162float(h0));
    bf16 l1 = __float2bfloat16(a1 - __bfloat162float(h1));
    bf16 l2 = __float2bfloat16(a2 - __bfloat162float(h2));
    bf16 l3 = __float2bfloat16(a3 - __bfloat162float(h3));
    __nv_bfloat162 hA = __halves2bfloat162(h0, h1), hB = __halves2bfloat162(h2, h3);
    __nv_bfloat162 lA = __halves2bfloat162(l0, l1), lB = __halves2bfloat162(l2, l3);
    *(uint2*)(g_agh + w * 128 + lane * 4) = make_uint2(*(uint32_t*)&hA, *(uint32_t*)&hB);
    *(uint2*)(g_agl + w * 128 + lane * 4) = make_uint2(*(uint32_t*)&lA, *(uint32_t*)&lB);
}

// ---------------------------------------------------------------------------
// Tensor-core GEMM via mma.sync (bf16 3-term split, fp32 accum).
// cp.async double-buffered pipeline: stage chunk c+1 while computing chunk c.
// Block 128x128, 8 warps (4x2), warp tile 32x64. K chunk = 32.
// ---------------------------------------------------------------------------
constexpr int A_ST = 40;    // bf16 stride (pad 32->40)
constexpr int W_ST = 136;   // bf16 stride (pad 128->136)
constexpr int A_BUF = 128 * A_ST;                 // 5120 elements
constexpr int W_BUF = 32 * W_ST;                  // 4352 elements
constexpr int SBUF  = 2 * A_BUF + 2 * W_BUF;      // 18944 elements per stage
constexpr int GEMM_SMEM_BYTES = 2 * SBUF * 2;     // 75776 bytes

__global__ void __launch_bounds__(256)
gemm_mma(int a1sel, int a2sel, int wbase0, int wbase1,
         const float* __restrict__ bias, int relu, int outmode,
         int outsel0, int outsel1, int M) {
    extern __shared__ __align__(16) bf16 dyn[];

    const int wbase  = (blockIdx.y == 0) ? wbase0 : wbase1;
    const int outsel = (blockIdx.y == 0) ? outsel0 : outsel1;

    const int tid = threadIdx.x;
    const int wid = tid >> 5;
    const int lane = tid & 31;
    const int wr = wid >> 1;
    const int wc = wid & 1;
    const int m0 = blockIdx.x * 128;
    const int lrow = lane & 15;
    const int lhalf = lane >> 4;

    const uint32_t dynb = smem_u32(dyn);
    // buffer b bases (bytes)
    const uint32_t bAh0 = dynb;
    const uint32_t bAl0 = dynb + A_BUF * 2;
    const uint32_t bWh0 = dynb + 2 * A_BUF * 2;
    const uint32_t bWl0 = dynb + (2 * A_BUF + W_BUF) * 2;
    const uint32_t bstep = SBUF * 2;

    const int nch = (a2sel < 0) ? 4 : 8;

    // Per-thread staging coordinates
    const int ar0 = tid >> 2, aq0 = (tid & 3) * 8;            // A piece 0
    const int ar1 = (tid + 256) >> 2, aq1 = aq0;              // A piece 1
    const int wr0 = tid >> 4, wq0 = (tid & 15) * 8;           // W piece 0
    const int wr1 = (tid + 256) >> 4, wq1 = wq0;              // W piece 1

    // Staging: chunk cc into buffer b
    auto stage = [&](int cc, int b) {
        const int half = (nch == 8 && cc >= 4) ? 1 : 0;
        const int psel = half ? a2sel : a1sel;
        const bf16* Ah = pair_h(psel);
        const bf16* Al = pair_l(psel);
        const int kbase = (cc & 3) * 32;
        const bf16* wh = g_wh + (size_t)(wbase + cc) * 4096;
        const bf16* wl = g_wl + (size_t)(wbase + cc) * 4096;
        uint32_t base = (uint32_t)b * bstep;

        int gr0 = m0 + ar0, gr1 = m0 + ar1;
        int sz0 = (gr0 < M) ? 16 : 0;
        int sz1 = (gr1 < M) ? 16 : 0;
        int cg0 = min(gr0, M - 1), cg1 = min(gr1, M - 1);
        uint32_t d0 = (uint32_t)((ar0 * A_ST + aq0) * 2);
        uint32_t d1 = (uint32_t)((ar1 * A_ST + aq1) * 2);
        cpasync16(bAh0 + base + d0, Ah + (size_t)cg0 * 128 + kbase + aq0, sz0);
        cpasync16(bAh0 + base + d1, Ah + (size_t)cg1 * 128 + kbase + aq1, sz1);
        cpasync16(bAl0 + base + d0, Al + (size_t)cg0 * 128 + kbase + aq0, sz0);
        cpasync16(bAl0 + base + d1, Al + (size_t)cg1 * 128 + kbase + aq1, sz1);
        uint32_t e0 = (uint32_t)((wr0 * W_ST + wq0) * 2);
        uint32_t e1 = (uint32_t)((wr1 * W_ST + wq1) * 2);
        cpasync16(bWh0 + base + e0, wh + wr0 * 128 + wq0, 16);
        cpasync16(bWh0 + base + e1, wh + wr1 * 128 + wq1, 16);
        cpasync16(bWl0 + base + e0, wl + wr0 * 128 + wq0, 16);
        cpasync16(bWl0 + base + e1, wl + wr1 * 128 + wq1, 16);
    };

    float acc[2][8][4];
#pragma unroll
    for (int i = 0; i < 2; i++)
#pragma unroll
        for (int j = 0; j < 8; j++)
#pragma unroll
            for (int k = 0; k < 4; k++) acc[i][j][k] = 0.f;

    stage(0, 0);
    CP_COMMIT();

    for (int c = 0; c < nch; c++) {
        const int cb = c & 1;
        if (c + 1 < nch) {
            stage(c + 1, cb ^ 1);
            CP_COMMIT();
            CP_WAIT1();
        } else {
            CP_WAIT0();
        }
        __syncthreads();

        const uint32_t base = (uint32_t)cb * bstep;
        const uint32_t aH = bAh0 + base, aL = bAl0 + base;
        const uint32_t wH = bWh0 + base, wL = bWl0 + base;
#pragma unroll
        for (int ks = 0; ks < 2; ks++) {
            uint32_t fH[2][4], fL[2][4];
#pragma unroll
            for (int mt = 0; mt < 2; mt++) {
                uint32_t off = (uint32_t)(((32 * wr + 16 * mt + lrow) * A_ST +
                                           ks * 16 + 8 * lhalf) * 2);
                ldmx4(fH[mt], aH + off);
                ldmx4(fL[mt], aL + off);
            }
#pragma unroll
            for (int ng = 0; ng < 4; ng++) {
                uint32_t bH[4], bL[4];
                uint32_t off = (uint32_t)(((ks * 16 + lrow) * W_ST +
                                           64 * wc + 16 * ng + 8 * lhalf) * 2);
                ldmx4t(bH, wH + off);
                ldmx4t(bL, wL + off);
#pragma unroll
                for (int mt = 0; mt < 2; mt++) {
                    mma16816(acc[mt][2 * ng],     fH[mt], bH);
                    mma16816(acc[mt][2 * ng],     fH[mt], bL);
                    mma16816(acc[mt][2 * ng],     fL[mt], bH);
                    mma16816(acc[mt][2 * ng + 1], fH[mt], bH + 2);
                    mma16816(acc[mt][2 * ng + 1], fH[mt], bL + 2);
                    mma16816(acc[mt][2 * ng + 1], fL[mt], bH + 2);
                }
            }
        }
        __syncthreads();
    }

    // Epilogue
    float* Cf = (outmode == 1) ? ((outsel == 0) ? g_b0 : g_b1) : nullptr;
    bf16* oh = (outmode == 0) ? (bf16*)pair_h(outsel) : nullptr;
    bf16* ol = (outmode == 0) ? (bf16*)pair_l(outsel) : nullptr;

#pragma unroll
    for (int mt = 0; mt < 2; mt++) {
#pragma unroll
        for (int nt = 0; nt < 8; nt++) {
            int col = 64 * wc + 8 * nt + 2 * (lane & 3);
            float bb0 = bias ? bias[col] : 0.f;
            float bb1 = bias ? bias[col + 1] : 0.f;
#pragma unroll
            for (int h = 0; h < 2; h++) {
                int r = m0 + 32 * wr + 16 * mt + (lane >> 2) + 8 * h;
                if (r < M) {
                    float v0 = acc[mt][nt][2 * h]     + bb0;
                    float v1 = acc[mt][nt][2 * h + 1] + bb1;
                    if (relu) { v0 = fmaxf(v0, 0.f); v1 = fmaxf(v1, 0.f); }
                    if (outmode == 1) {
                        *(float2*)(Cf + (size_t)r * 128 + col) = make_float2(v0, v1);
                    } else {
                        bf16 h0 = __float2bfloat16(v0);
                        bf16 h1 = __float2bfloat16(v1);
                        bf16 l0 = __float2bfloat16(v0 - __bfloat162float(h0));
                        bf16 l1 = __float2bfloat16(v1 - __bfloat162float(h1));
                        __nv_bfloat162 hp = __halves2bfloat162(h0, h1);
                        __nv_bfloat162 lp = __halves2bfloat162(l0, l1);
                        *(uint32_t*)(oh + (size_t)r * 128 + col) = *(uint32_t*)&hp;
                        *(uint32_t*)(ol + (size_t)r * 128 + col) = *(uint32_t*)&lp;
                    }
                }
            }
        }
    }
}

// ---------------------------------------------------------------------------
// Edge predict: y[e] = relu(U[i] + V[j] + qb1) . qW2 + qb2  (one warp/edge)
// ---------------------------------------------------------------------------
__global__ void predict_kernel(const void* __restrict__ pidx,
                               const float* __restrict__ qb1,
                               const float* __restrict__ qW2,
                               const float* __restrict__ qb2,
                               float* __restrict__ y, int EP) {
    int w = (blockIdx.x * blockDim.x + threadIdx.x) >> 5;
    int lane = threadIdx.x & 31;
    if (w >= EP) return;
    int is64 = g_pi64;
    int i = getidx(pidx, w, is64);
    int j = getidx(pidx, (long long)EP + w, is64);
    float4 u = ((const float4*)g_b0)[i * 32 + lane];
    float4 v = ((const float4*)g_b1)[j * 32 + lane];
    float4 b = ((const float4*)qb1)[lane];
    float4 q = ((const float4*)qW2)[lane];
    float h0 = fmaxf(u.x + v.x + b.x, 0.f);
    float h1 = fmaxf(u.y + v.y + b.y, 0.f);
    float h2 = fmaxf(u.z + v.z + b.z, 0.f);
    float h3 = fmaxf(u.w + v.w + b.w, 0.f);
    float p = h0 * q.x + h1 * q.y + h2 * q.z + h3 * q.w;
#pragma unroll
    for (int o = 16; o > 0; o >>= 1) p += __shfl_xor_sync(0xFFFFFFFFu, p, o);
    if (lane == 0) y[w] = p + qb2[0];
}

// ---------------------------------------------------------------------------
// Launch
// ---------------------------------------------------------------------------
extern "C" void kernel_launch(void* const* d_in, const int* in_sizes, int n_in,
                              void* d_out, int out_size) {
    const float* x   = (const float*)d_in[0];
    const void*  ei  = d_in[2];
    const void*  pi  = d_in[3];
    const float* Wl  = (const float*)d_in[4];
    const float* bl  = (const float*)d_in[5];
    const float* Wr  = (const float*)d_in[6];
    // d_in[7..10]: edge-update MLP params — dead code w.r.t. the output
    const float* pW1 = (const float*)d_in[11];
    const float* pb1 = (const float*)d_in[12];
    const float* pW2 = (const float*)d_in[13];
    const float* pb2 = (const float*)d_in[14];
    const float* qW1 = (const float*)d_in[15];
    const float* qb1 = (const float*)d_in[16];
    const float* qW2 = (const float*)d_in[17];
    const float* qb2 = (const float*)d_in[18];

    const int N  = in_sizes[0] / 128;
    const int E  = in_sizes[2] / 2;
    const int EP = in_sizes[3] / 2;
    const int L  = in_sizes[4] / (128 * 128);

    cudaFuncSetAttribute(gemm_mma, cudaFuncAttributeMaxDynamicSharedMemorySize,
                         GEMM_SMEM_BYTES);

    // Weight pack + x conversion (independent of CSR)
    prep_w_kernel<<<(40 * 4096 + 255) / 256, 256>>>(Wl, Wr, pW1, pW2, qW1);
    convert_x_kernel<<<(N * 32 + 255) / 256, 256>>>(x, N * 32);

    // CSR build
    init_kernel<<<(N + 255) / 256, 256>>>((const unsigned int*)ei,
                                          (const unsigned int*)pi, N);
    count_kernel<<<(E + 255) / 256, 256>>>(ei, E);
    segment_kernel<<<(N + 255) / 256, 256>>>(N);
    fill_kernel<<<(E + 255) / 256, 256>>>(ei, E);

    const int gemm_blocks = (N + 127) / 128;
    const int aggr_blocks = (N * 32 + 255) / 256;

    // GNN layers: cur pair sel 0(x) -> 1 -> 2 -> 1
    int cur = 0;
    for (int l = 0; l < L; l++) {
        int nxt = (l == 0) ? 1 : (l == 1) ? 2 : 1;
        aggr_kernel<<<aggr_blocks, 256>>>(cur, N);
        gemm_mma<<<dim3(gemm_blocks, 1), 256, GEMM_SMEM_BYTES>>>(
            3, cur, l * 8, 0, bl + l * 128, 1, 0, nxt, 0, N);
        cur = nxt;
    }
    // cur = 1. Post MLP: g3: p0 -> p1 (relu); g4: p1 -> p0 (no relu)
    gemm_mma<<<dim3(gemm_blocks, 1), 256, GEMM_SMEM_BYTES>>>(
        1, -1, 24, 0, pb1, 1, 0, 2, 0, N);
    gemm_mma<<<dim3(gemm_blocks, 1), 256, GEMM_SMEM_BYTES>>>(
        2, -1, 28, 0, pb2, 0, 0, 1, 0, N);
    // U/V batched: y=0 -> wbase 32 -> g_b0 ; y=1 -> wbase 36 -> g_b1 (fp32)
    gemm_mma<<<dim3(gemm_blocks, 2), 256, GEMM_SMEM_BYTES>>>(
        1, -1, 32, 36, nullptr, 0, 1, 0, 1, N);

    predict_kernel<<<(EP * 32 + 255) / 256, 256>>>(pi, qb1, qW2, qb2, (float*)d_out, EP);
}

// round 9
// speedup vs baseline: 2.3823x; 1.0147x over previous
#include <cuda_runtime.h>
#include <cuda_bf16.h>
#include <cstdint>

typedef __nv_bfloat16 bf16;

// Problem-fixed sizes: N=50000, E=600000, EP=200000, D=128, L=3
constexpr int NMAX = 50000;
constexpr int EMAX = 600000;

// fp32 scratch (U, V for predict)
__device__ __align__(16) float g_b0[NMAX * 128];
__device__ __align__(16) float g_b1[NMAX * 128];
// bf16 hi/lo node-feature pairs: 0=x, 1=p0, 2=p1, 3=ag, 4=tmp(weights)
__device__ __align__(16) bf16 g_xh[NMAX * 128];
__device__ __align__(16) bf16 g_xl[NMAX * 128];
__device__ __align__(16) bf16 g_p0h[NMAX * 128];
__device__ __align__(16) bf16 g_p0l[NMAX * 128];
__device__ __align__(16) bf16 g_p1h[NMAX * 128];
__device__ __align__(16) bf16 g_p1l[NMAX * 128];
__device__ __align__(16) bf16 g_agh[NMAX * 128];
__device__ __align__(16) bf16 g_agl[NMAX * 128];
__device__ __align__(16) bf16 g_tmph[128 * 128];
__device__ __align__(16) bf16 g_tmpl[128 * 128];
// Packed weights: 44 chunks x 4096 bf16 ([k=32][n=128] plain layout)
// 0-23: layers (K=256 each), 24-27: pW1, 28-31: qW1a, 32-35: qW1b,
// 36-39: W_U (composite, device-computed), 40-43: W_V
__device__ __align__(16) bf16 g_wh[44 * 4096];
__device__ __align__(16) bf16 g_wl[44 * 4096];
__device__ float g_cvec[128];   // qb1 + pb2@qW1a + pb2@qW1b
// CSR
__device__ int   g_counts[NMAX];
__device__ int   g_offsets[NMAX];
__device__ int   g_cursor[NMAX];
__device__ float g_invdeg[NMAX];
__device__ int   g_csr[EMAX];
__device__ int   g_total;
__device__ int   g_ei64;
__device__ int   g_pi64;

__device__ __forceinline__ const bf16* pair_h(int s) {
    if (s == 0) return g_xh;
    if (s == 1) return g_p0h;
    if (s == 2) return g_p1h;
    if (s == 3) return g_agh;
    return g_tmph;
}
__device__ __forceinline__ const bf16* pair_l(int s) {
    if (s == 0) return g_xl;
    if (s == 1) return g_p0l;
    if (s == 2) return g_p1l;
    if (s == 3) return g_agl;
    return g_tmpl;
}

__device__ __forceinline__ int getidx(const void* p, long long pos, int is64) {
    if (is64) return (int)((const long long*)p)[pos];
    return ((const int*)p)[pos];
}

__device__ __forceinline__ uint32_t smem_u32(const void* p) {
    uint32_t a;
    asm("{ .reg .u64 t; cvta.to.shared.u64 t, %1; cvt.u32.u64 %0, t; }" : "=r"(a) : "l"(p));
    return a;
}
__device__ __forceinline__ void ldmx4(uint32_t* r, uint32_t addr) {
    asm volatile("ldmatrix.sync.aligned.m8n8.x4.shared.b16 {%0,%1,%2,%3}, [%4];"
                 : "=r"(r[0]), "=r"(r[1]), "=r"(r[2]), "=r"(r[3]) : "r"(addr));
}
__device__ __forceinline__ void ldmx4t(uint32_t* r, uint32_t addr) {
    asm volatile("ldmatrix.sync.aligned.m8n8.x4.trans.shared.b16 {%0,%1,%2,%3}, [%4];"
                 : "=r"(r[0]), "=r"(r[1]), "=r"(r[2]), "=r"(r[3]) : "r"(addr));
}
__device__ __forceinline__ void mma16816(float* c, const uint32_t* a, const uint32_t* b) {
    asm volatile(
        "mma.sync.aligned.m16n8k16.row.col.f32.bf16.bf16.f32 "
        "{%0,%1,%2,%3}, {%4,%5,%6,%7}, {%8,%9}, {%0,%1,%2,%3};"
        : "+f"(c[0]), "+f"(c[1]), "+f"(c[2]), "+f"(c[3])
        : "r"(a[0]), "r"(a[1]), "r"(a[2]), "r"(a[3]), "r"(b[0]), "r"(b[1]));
}
__device__ __forceinline__ void cpasync16(uint32_t dst, const void* src, int srcsize) {
    asm volatile("cp.async.cg.shared.global [%0], [%1], 16, %2;"
                 :: "r"(dst), "l"(src), "r"(srcsize) : "memory");
}
#define CP_COMMIT() asm volatile("cp.async.commit_group;" ::: "memory")
#define CP_WAIT1()  asm volatile("cp.async.wait_group 1;" ::: "memory")
#define CP_WAIT0()  asm volatile("cp.async.wait_group 0;" ::: "memory")

// ---------------------------------------------------------------------------
// Weight prep: pack + transpose + bf16-split.
// cg 0-23: layers; 24-27: pW1; 28-31: qW1a; 32-35: qW1b; 36-39: pW2 -> tmp pair
// ---------------------------------------------------------------------------
__global__ void prep_w_kernel(const float* __restrict__ Wl, const float* __restrict__ Wr,
                              const float* __restrict__ pW1, const float* __restrict__ pW2,
                              const float* __restrict__ qW1) {
    int t = blockIdx.x * blockDim.x + threadIdx.x;
    if (t >= 40 * 4096) return;
    int cg = t >> 12;
    int within = t & 4095;
    int kl = within >> 7;      // 0..31
    int n  = within & 127;
    float v;
    if (cg < 24) {
        int g = cg >> 3, c = cg & 7;
        int kk = c * 32 + kl;
        v = (kk < 128) ? Wl[g * 16384 + kk * 128 + n]
                       : Wr[g * 16384 + (kk - 128) * 128 + n];
    } else if (cg < 28) {
        int kk = (cg - 24) * 32 + kl;
        v = pW1[kk * 128 + n];
    } else if (cg < 32) {
        int kk = (cg - 28) * 32 + kl;
        v = qW1[kk * 128 + n];
    } else if (cg < 36) {
        int kk = (cg - 32) * 32 + kl;
        v = qW1[(128 + kk) * 128 + n];
    } else {
        // pW2 -> tmp pair (plain row-major A operand for the composite GEMM)
        int kk = (cg - 36) * 32 + kl;
        v = pW2[kk * 128 + n];
        bf16 hi2 = __float2bfloat16(v);
        bf16 lo2 = __float2bfloat16(v - __bfloat162float(hi2));
        g_tmph[kk * 128 + n] = hi2;
        g_tmpl[kk * 128 + n] = lo2;
        return;
    }
    bf16 hi = __float2bfloat16(v);
    bf16 lo = __float2bfloat16(v - __bfloat162float(hi));
    g_wh[cg * 4096 + kl * 128 + n] = hi;
    g_wl[cg * 4096 + kl * 128 + n] = lo;
}

// ---------------------------------------------------------------------------
// Bias composition: cvec = qb1 + pb2@qW1a + pb2@qW1b  (1 block, 128 threads)
// ---------------------------------------------------------------------------
__global__ void cvec_kernel(const float* __restrict__ qW1,
                            const float* __restrict__ pb2,
                            const float* __restrict__ qb1) {
    int j = threadIdx.x;
    float c = qb1[j];
    for (int k = 0; k < 128; k++) {
        float p = pb2[k];
        c += p * (qW1[k * 128 + j] + qW1[(128 + k) * 128 + j]);
    }
    g_cvec[j] = c;
}

// ---------------------------------------------------------------------------
// Convert x (fp32) -> bf16 hi/lo pair (sel 0)
// ---------------------------------------------------------------------------
__global__ void convert_x_kernel(const float* __restrict__ x, int n32) {
    int i = blockIdx.x * blockDim.x + threadIdx.x;
    if (i >= n32) return;
    float4 v = ((const float4*)x)[i];
    bf16 h0 = __float2bfloat16(v.x), h1 = __float2bfloat16(v.y);
    bf16 h2 = __float2bfloat16(v.z), h3 = __float2bfloat16(v.w);
    bf16 l0 = __float2bfloat16(v.x - __bfloat162float(h0));
    bf16 l1 = __float2bfloat16(v.y - __bfloat162float(h1));
    bf16 l2 = __float2bfloat16(v.z - __bfloat162float(h2));
    bf16 l3 = __float2bfloat16(v.w - __bfloat162float(h3));
    __nv_bfloat162 hA = __halves2bfloat162(h0, h1), hB = __halves2bfloat162(h2, h3);
    __nv_bfloat162 lA = __halves2bfloat162(l0, l1), lB = __halves2bfloat162(l2, l3);
    ((uint2*)g_xh)[i] = make_uint2(*(uint32_t*)&hA, *(uint32_t*)&hB);
    ((uint2*)g_xl)[i] = make_uint2(*(uint32_t*)&lA, *(uint32_t*)&lB);
}

// ---------------------------------------------------------------------------
// Init / CSR build
// ---------------------------------------------------------------------------
__global__ void init_kernel(const unsigned int* __restrict__ eiw,
                            const unsigned int* __restrict__ piw, int n) {
    int i = blockIdx.x * blockDim.x + threadIdx.x;
    if (i < n) g_counts[i] = 0;
    if (blockIdx.x == 0) {
        unsigned ve = eiw[2 * threadIdx.x + 1];
        unsigned vp = piw[2 * threadIdx.x + 1];
        int e0 = __syncthreads_and(ve == 0u);
        int p0 = __syncthreads_and(vp == 0u);
        if (threadIdx.x == 0) { g_ei64 = e0; g_pi64 = p0; g_total = 0; }
    }
}

__global__ void count_kernel(const void* __restrict__ ei, int E) {
    int e = blockIdx.x * blockDim.x + threadIdx.x;
    if (e < E) atomicAdd(&g_counts[getidx(ei, (long long)E + e, g_ei64)], 1);
}

__global__ void segment_kernel(int n) {
    __shared__ int wsum[8];
    __shared__ int blockbase;
    int i = blockIdx.x * 256 + threadIdx.x;
    int lane = threadIdx.x & 31;
    int wid  = threadIdx.x >> 5;
    int c = (i < n) ? g_counts[i] : 0;
    int s = c;
#pragma unroll
    for (int off = 1; off < 32; off <<= 1) {
        int v = __shfl_up_sync(0xFFFFFFFFu, s, off);
        if (lane >= off) s += v;
    }
    if (lane == 31) wsum[wid] = s;
    __syncthreads();
    if (wid == 0) {
        int v = (lane < 8) ? wsum[lane] : 0;
#pragma unroll
        for (int off = 1; off < 8; off <<= 1) {
            int t2 = __shfl_up_sync(0xFFFFFFFFu, v, off);
            if (lane >= off) v += t2;
        }
        if (lane < 8) wsum[lane] = v;
        int total = __shfl_sync(0xFFFFFFFFu, v, 7);
        if (lane == 0) blockbase = atomicAdd(&g_total, total);
    }
    __syncthreads();
    if (i < n) {
        int excl = blockbase + (wid > 0 ? wsum[wid - 1] : 0) + s - c;
        g_offsets[i] = excl;
        g_cursor[i]  = excl;
        g_invdeg[i]  = 1.0f / (float)max(c, 1);
    }
}

__global__ void fill_kernel(const void* __restrict__ ei, int E) {
    int e = blockIdx.x * blockDim.x + threadIdx.x;
    if (e < E) {
        int s = getidx(ei, e, g_ei64);
        int d = getidx(ei, (long long)E + e, g_ei64);
        g_csr[atomicAdd(&g_cursor[d], 1)] = s;
    }
}

// ---------------------------------------------------------------------------
// Mean aggregation over bf16 pairs -> ag bf16 pair. One warp/node.
// ---------------------------------------------------------------------------
__global__ void aggr_kernel(int xsel, int n) {
    int w = (blockIdx.x * blockDim.x + threadIdx.x) >> 5;
    int lane = threadIdx.x & 31;
    if (w >= n) return;
    const bf16* xh = pair_h(xsel);
    const bf16* xl = pair_l(xsel);
    int beg = g_offsets[w];
    int cnt = g_counts[w];
    float a0 = 0.f, a1 = 0.f, a2 = 0.f, a3 = 0.f;
    for (int j = beg; j < beg + cnt; ++j) {
        int s = g_csr[j];
        uint2 uh = *(const uint2*)(xh + s * 128 + lane * 4);
        uint2 ul = *(const uint2*)(xl + s * 128 + lane * 4);
        __nv_bfloat162 h01 = *(__nv_bfloat162*)&uh.x;
        __nv_bfloat162 h23 = *(__nv_bfloat162*)&uh.y;
        __nv_bfloat162 l01 = *(__nv_bfloat162*)&ul.x;
        __nv_bfloat162 l23 = *(__nv_bfloat162*)&ul.y;
        a0 += __low2float(h01)  + __low2float(l01);
        a1 += __high2float(h01) + __high2float(l01);
        a2 += __low2float(h23)  + __low2float(l23);
        a3 += __high2float(h23) + __high2float(l23);
    }
    float inv = g_invdeg[w];
    a0 *= inv; a1 *= inv; a2 *= inv; a3 *= inv;
    bf16 h0 = __float2bfloat16(a0), h1 = __float2bfloat16(a1);
    bf16 h2 = __float2bfloat16(a2), h3 = __float2bfloat16(a3);
    bf16 l0 = __float2bfloat16(a0 - __bfloat162float(h0));
    bf16 l1 = __float2bfloat16(a1 - __bfloat162float(h1));
    bf16 l2 = __float2bfloat16(a2 - __bfloat162float(h2));
    bf16 l3 = __float2bfloat16(a3 - __bfloat162float(h3));
    __nv_bfloat162 hA = __halves2bfloat162(h0, h1), hB = __halves2bfloat162(h2, h3);
    __nv_bfloat162 lA = __halves2bfloat162(l0, l1), lB = __halves2bfloat162(l2, l3);
    *(uint2*)(g_agh + w * 128 + lane * 4) = make_uint2(*(uint32_t*)&hA, *(uint32_t*)&hB);
    *(uint2*)(g_agl + w * 128 + lane * 4) = make_uint2(*(uint32_t*)&lA, *(uint32_t*)&lB);
}

// ---------------------------------------------------------------------------
// Tensor-core GEMM via mma.sync (bf16 3-term split, fp32 accum).
// cp.async double-buffered pipeline. Block 128x128, 8 warps, warp tile 32x64.
// outmode 0: bf16 pair -> outsel; 1: fp32 -> g_b0/g_b1;
//         2: bf16 pair -> weight chunks at chunk-base outsel (composite).
// ---------------------------------------------------------------------------
constexpr int A_ST = 40;
constexpr int W_ST = 136;
constexpr int A_BUF = 128 * A_ST;
constexpr int W_BUF = 32 * W_ST;
constexpr int SBUF  = 2 * A_BUF + 2 * W_BUF;
constexpr int GEMM_SMEM_BYTES = 2 * SBUF * 2;     // 75776 bytes

__global__ void __launch_bounds__(256)
gemm_mma(int a1sel, int a2sel, int wbase0, int wbase1,
         const float* __restrict__ bias, int relu, int outmode,
         int outsel0, int outsel1, int M) {
    extern __shared__ __align__(16) bf16 dyn[];

    const int wbase  = (blockIdx.y == 0) ? wbase0 : wbase1;
    const int outsel = (blockIdx.y == 0) ? outsel0 : outsel1;

    const int tid = threadIdx.x;
    const int wid = tid >> 5;
    const int lane = tid & 31;
    const int wr = wid >> 1;
    const int wc = wid & 1;
    const int m0 = blockIdx.x * 128;
    const int lrow = lane & 15;
    const int lhalf = lane >> 4;

    const uint32_t dynb = smem_u32(dyn);
    const uint32_t bAh0 = dynb;
    const uint32_t bAl0 = dynb + A_BUF * 2;
    const uint32_t bWh0 = dynb + 2 * A_BUF * 2;
    const uint32_t bWl0 = dynb + (2 * A_BUF + W_BUF) * 2;
    const uint32_t bstep = SBUF * 2;

    const int nch = (a2sel < 0) ? 4 : 8;

    const int ar0 = tid >> 2, aq0 = (tid & 3) * 8;
    const int ar1 = (tid + 256) >> 2, aq1 = aq0;
    const int wr0 = tid >> 4, wq0 = (tid & 15) * 8;
    const int wr1 = (tid + 256) >> 4, wq1 = wq0;

    auto stage = [&](int cc, int b) {
        const int half = (nch == 8 && cc >= 4) ? 1 : 0;
        const int psel = half ? a2sel : a1sel;
        const bf16* Ah = pair_h(psel);
        const bf16* Al = pair_l(psel);
        const int kbase = (cc & 3) * 32;
        const bf16* wh = g_wh + (size_t)(wbase + cc) * 4096;
        const bf16* wl = g_wl + (size_t)(wbase + cc) * 4096;
        uint32_t base = (uint32_t)b * bstep;

        int gr0 = m0 + ar0, gr1 = m0 + ar1;
        int sz0 = (gr0 < M) ? 16 : 0;
        int sz1 = (gr1 < M) ? 16 : 0;
        int cg0 = min(gr0, M - 1), cg1 = min(gr1, M - 1);
        uint32_t d0 = (uint32_t)((ar0 * A_ST + aq0) * 2);
        uint32_t d1 = (uint32_t)((ar1 * A_ST + aq1) * 2);
        cpasync16(bAh0 + base + d0, Ah + (size_t)cg0 * 128 + kbase + aq0, sz0);
        cpasync16(bAh0 + base + d1, Ah + (size_t)cg1 * 128 + kbase + aq1, sz1);
        cpasync16(bAl0 + base + d0, Al + (size_t)cg0 * 128 + kbase + aq0, sz0);
        cpasync16(bAl0 + base + d1, Al + (size_t)cg1 * 128 + kbase + aq1, sz1);
        uint32_t e0 = (uint32_t)((wr0 * W_ST + wq0) * 2);
        uint32_t e1 = (uint32_t)((wr1 * W_ST + wq1) * 2);
        cpasync16(bWh0 + base + e0, wh + wr0 * 128 + wq0, 16);
        cpasync16(bWh0 + base + e1, wh + wr1 * 128 + wq1, 16);
        cpasync16(bWl0 + base + e0, wl + wr0 * 128 + wq0, 16);
        cpasync16(bWl0 + base + e1, wl + wr1 * 128 + wq1, 16);
    };

    float acc[2][8][4];
#pragma unroll
    for (int i = 0; i < 2; i++)
#pragma unroll
        for (int j = 0; j < 8; j++)
#pragma unroll
            for (int k = 0; k < 4; k++) acc[i][j][k] = 0.f;

    stage(0, 0);
    CP_COMMIT();

    for (int c = 0; c < nch; c++) {
        const int cb = c & 1;
        if (c + 1 < nch) {
            stage(c + 1, cb ^ 1);
            CP_COMMIT();
            CP_WAIT1();
        } else {
            CP_WAIT0();
        }
        __syncthreads();

        const uint32_t base = (uint32_t)cb * bstep;
        const uint32_t aH = bAh0 + base, aL = bAl0 + base;
        const uint32_t wH = bWh0 + base, wL = bWl0 + base;
#pragma unroll
        for (int ks = 0; ks < 2; ks++) {
            uint32_t fH[2][4], fL[2][4];
#pragma unroll
            for (int mt = 0; mt < 2; mt++) {
                uint32_t off = (uint32_t)(((32 * wr + 16 * mt + lrow) * A_ST +
                                           ks * 16 + 8 * lhalf) * 2);
                ldmx4(fH[mt], aH + off);
                ldmx4(fL[mt], aL + off);
            }
#pragma unroll
            for (int ng = 0; ng < 4; ng++) {
                uint32_t bH[4], bL[4];
                uint32_t off = (uint32_t)(((ks * 16 + lrow) * W_ST +
                                           64 * wc + 16 * ng + 8 * lhalf) * 2);
                ldmx4t(bH, wH + off);
                ldmx4t(bL, wL + off);
#pragma unroll
                for (int mt = 0; mt < 2; mt++) {
                    mma16816(acc[mt][2 * ng],     fH[mt], bH);
                    mma16816(acc[mt][2 * ng],     fH[mt], bL);
                    mma16816(acc[mt][2 * ng],     fL[mt], bH);
                    mma16816(acc[mt][2 * ng + 1], fH[mt], bH + 2);
                    mma16816(acc[mt][2 * ng + 1], fH[mt], bL + 2);
                    mma16816(acc[mt][2 * ng + 1], fL[mt], bH + 2);
                }
            }
        }
        __syncthreads();
    }

    // Epilogue
    float* Cf = (outmode == 1) ? ((outsel == 0) ? g_b0 : g_b1) : nullptr;
    bf16* oh = (outmode == 0) ? (bf16*)pair_h(outsel) : nullptr;
    bf16* ol = (outmode == 0) ? (bf16*)pair_l(outsel) : nullptr;

#pragma unroll
    for (int mt = 0; mt < 2; mt++) {
#pragma unroll
        for (int nt = 0; nt < 8; nt++) {
            int col = 64 * wc + 8 * nt + 2 * (lane & 3);
            float bb0 = bias ? bias[col] : 0.f;
            float bb1 = bias ? bias[col + 1] : 0.f;
#pragma unroll
            for (int h = 0; h < 2; h++) {
                int r = m0 + 32 * wr + 16 * mt + (lane >> 2) + 8 * h;
                if (r < M) {
                    float v0 = acc[mt][nt][2 * h]     + bb0;
                    float v1 = acc[mt][nt][2 * h + 1] + bb1;
                    if (relu) { v0 = fmaxf(v0, 0.f); v1 = fmaxf(v1, 0.f); }
                    if (outmode == 1) {
                        *(float2*)(Cf + (size_t)r * 128 + col) = make_float2(v0, v1);
                    } else {
                        bf16 h0 = __float2bfloat16(v0);
                        bf16 h1 = __float2bfloat16(v1);
                        bf16 l0 = __float2bfloat16(v0 - __bfloat162float(h0));
                        bf16 l1 = __float2bfloat16(v1 - __bfloat162float(h1));
                        __nv_bfloat162 hp = __halves2bfloat162(h0, h1);
                        __nv_bfloat162 lp = __halves2bfloat162(l0, l1);
                        if (outmode == 0) {
                            *(uint32_t*)(oh + (size_t)r * 128 + col) = *(uint32_t*)&hp;
                            *(uint32_t*)(ol + (size_t)r * 128 + col) = *(uint32_t*)&lp;
                        } else {
                            // outmode 2: write into weight chunk layout
                            size_t woff = (size_t)(outsel + (r >> 5)) * 4096 +
                                          (size_t)(r & 31) * 128 + col;
                            *(uint32_t*)(g_wh + woff) = *(uint32_t*)&hp;
                            *(uint32_t*)(g_wl + woff) = *(uint32_t*)&lp;
                        }
                    }
                }
            }
        }
    }
}

// ---------------------------------------------------------------------------
// Edge predict: y[e] = relu(U[i] + V[j] + cvec) . qW2 + qb2  (one warp/edge)
// ---------------------------------------------------------------------------
__global__ void predict_kernel(const void* __restrict__ pidx,
                               const float* __restrict__ qW2,
                               const float* __restrict__ qb2,
                               float* __restrict__ y, int EP) {
    int w = (blockIdx.x * blockDim.x + threadIdx.x) >> 5;
    int lane = threadIdx.x & 31;
    if (w >= EP) return;
    int is64 = g_pi64;
    int i = getidx(pidx, w, is64);
    int j = getidx(pidx, (long long)EP + w, is64);
    float4 u = ((const float4*)g_b0)[i * 32 + lane];
    float4 v = ((const float4*)g_b1)[j * 32 + lane];
    float4 b = ((const float4*)g_cvec)[lane];
    float4 q = ((const float4*)qW2)[lane];
    float h0 = fmaxf(u.x + v.x + b.x, 0.f);
    float h1 = fmaxf(u.y + v.y + b.y, 0.f);
    float h2 = fmaxf(u.z + v.z + b.z, 0.f);
    float h3 = fmaxf(u.w + v.w + b.w, 0.f);
    float p = h0 * q.x + h1 * q.y + h2 * q.z + h3 * q.w;
#pragma unroll
    for (int o = 16; o > 0; o >>= 1) p += __shfl_xor_sync(0xFFFFFFFFu, p, o);
    if (lane == 0) y[w] = p + qb2[0];
}

// ---------------------------------------------------------------------------
// Launch
// ---------------------------------------------------------------------------
extern "C" void kernel_launch(void* const* d_in, const int* in_sizes, int n_in,
                              void* d_out, int out_size) {
    const float* x   = (const float*)d_in[0];
    const void*  ei  = d_in[2];
    const void*  pi  = d_in[3];
    const float* Wl  = (const float*)d_in[4];
    const float* bl  = (const float*)d_in[5];
    const float* Wr  = (const float*)d_in[6];
    // d_in[7..10]: edge-update MLP params — dead code w.r.t. the output
    const float* pW1 = (const float*)d_in[11];
    const float* pb1 = (const float*)d_in[12];
    const float* pW2 = (const float*)d_in[13];
    const float* pb2 = (const float*)d_in[14];
    const float* qW1 = (const float*)d_in[15];
    const float* qb1 = (const float*)d_in[16];
    const float* qW2 = (const float*)d_in[17];
    const float* qb2 = (const float*)d_in[18];

    const int N  = in_sizes[0] / 128;
    const int E  = in_sizes[2] / 2;
    const int EP = in_sizes[3] / 2;
    const int L  = in_sizes[4] / (128 * 128);

    cudaFuncSetAttribute(gemm_mma, cudaFuncAttributeMaxDynamicSharedMemorySize,
                         GEMM_SMEM_BYTES);

    // Weight pack + x conversion + bias composition (independent of CSR)
    prep_w_kernel<<<(40 * 4096 + 255) / 256, 256>>>(Wl, Wr, pW1, pW2, qW1);
    convert_x_kernel<<<(N * 32 + 255) / 256, 256>>>(x, N * 32);
    cvec_kernel<<<1, 128>>>(qW1, pb2, qb1);

    // Composite weights: W_U = pW2@qW1a -> chunks 36-39, W_V = pW2@qW1b -> 40-43
    gemm_mma<<<dim3(1, 2), 256, GEMM_SMEM_BYTES>>>(
        4, -1, 28, 32, nullptr, 0, 2, 36, 40, 128);

    // CSR build
    init_kernel<<<(N + 255) / 256, 256>>>((const unsigned int*)ei,
                                          (const unsigned int*)pi, N);
    count_kernel<<<(E + 255) / 256, 256>>>(ei, E);
    segment_kernel<<<(N + 255) / 256, 256>>>(N);
    fill_kernel<<<(E + 255) / 256, 256>>>(ei, E);

    const int gemm_blocks = (N + 127) / 128;
    const int aggr_blocks = (N * 32 + 255) / 256;

    // GNN layers: cur pair sel 0(x) -> 1 -> 2 -> 1
    int cur = 0;
    for (int l = 0; l < L; l++) {
        int nxt = (l == 0) ? 1 : (l == 1) ? 2 : 1;
        aggr_kernel<<<aggr_blocks, 256>>>(cur, N);
        gemm_mma<<<dim3(gemm_blocks, 1), 256, GEMM_SMEM_BYTES>>>(
            3, cur, l * 8, 0, bl + l * 128, 1, 0, nxt, 0, N);
        cur = nxt;
    }
    // cur = 1. Post MLP first half: z = relu(p0@pW1 + pb1) -> sel 2
    gemm_mma<<<dim3(gemm_blocks, 1), 256, GEMM_SMEM_BYTES>>>(
        1, -1, 24, 0, pb1, 1, 0, 2, 0, N);
    // U/V from z with composite weights: y=0 -> W_U -> g_b0 ; y=1 -> W_V -> g_b1
    gemm_mma<<<dim3(gemm_blocks, 2), 256, GEMM_SMEM_BYTES>>>(
        2, -1, 36, 40, nullptr, 0, 1, 0, 1, N);

    predict_kernel<<<(EP * 32 + 255) / 256, 256>>>(pi, qW2, qb2, (float*)d_out, EP);
}

// round 10
// speedup vs baseline: 2.7559x; 1.1568x over previous
#include <cuda_runtime.h>
#include <cuda_bf16.h>
#include <cstdint>

typedef __nv_bfloat16 bf16;

// Problem-fixed sizes: N=50000, E=600000, EP=200000, D=128, L=3
constexpr int NMAX = 50000;
constexpr int EMAX = 600000;

// fp32 scratch (U, V for predict)
__device__ __align__(16) float g_b0[NMAX * 128];
__device__ __align__(16) float g_b1[NMAX * 128];
// bf16 hi/lo node-feature pairs: 0=x, 1=p0, 2=p1, 3=ag
__device__ __align__(16) bf16 g_xh[NMAX * 128];
__device__ __align__(16) bf16 g_xl[NMAX * 128];
__device__ __align__(16) bf16 g_p0h[NMAX * 128];
__device__ __align__(16) bf16 g_p0l[NMAX * 128];
__device__ __align__(16) bf16 g_p1h[NMAX * 128];
__device__ __align__(16) bf16 g_p1l[NMAX * 128];
__device__ __align__(16) bf16 g_agh[NMAX * 128];
__device__ __align__(16) bf16 g_agl[NMAX * 128];
// Packed weights: 44 chunks x 4096 bf16 ([k=32][n=128] plain layout)
// 0-23: layers (K=256 each), 24-27: pW1, 28-31: qW1a, 32-35: qW1b,
// 36-39: W_U (composite, device-computed fp32), 40-43: W_V
__device__ __align__(16) bf16 g_wh[44 * 4096];
__device__ __align__(16) bf16 g_wl[44 * 4096];
__device__ float g_cvec[128];   // qb1 + pb2@qW1a + pb2@qW1b
// CSR
__device__ int   g_counts[NMAX];
__device__ int   g_offsets[NMAX];
__device__ int   g_cursor[NMAX];
__device__ float g_invdeg[NMAX];
__device__ int   g_csr[EMAX];
__device__ int   g_total;
__device__ int   g_ei64;
__device__ int   g_pi64;

__device__ __forceinline__ const bf16* pair_h(int s) {
    if (s == 0) return g_xh;
    if (s == 1) return g_p0h;
    if (s == 2) return g_p1h;
    return g_agh;
}
__device__ __forceinline__ const bf16* pair_l(int s) {
    if (s == 0) return g_xl;
    if (s == 1) return g_p0l;
    if (s == 2) return g_p1l;
    return g_agl;
}

__device__ __forceinline__ int getidx(const void* p, long long pos, int is64) {
    if (is64) return (int)((const long long*)p)[pos];
    return ((const int*)p)[pos];
}

__device__ __forceinline__ uint32_t smem_u32(const void* p) {
    uint32_t a;
    asm("{ .reg .u64 t; cvta.to.shared.u64 t, %1; cvt.u32.u64 %0, t; }" : "=r"(a) : "l"(p));
    return a;
}
__device__ __forceinline__ void ldmx4(uint32_t* r, uint32_t addr) {
    asm volatile("ldmatrix.sync.aligned.m8n8.x4.shared.b16 {%0,%1,%2,%3}, [%4];"
                 : "=r"(r[0]), "=r"(r[1]), "=r"(r[2]), "=r"(r[3]) : "r"(addr));
}
__device__ __forceinline__ void ldmx4t(uint32_t* r, uint32_t addr) {
    asm volatile("ldmatrix.sync.aligned.m8n8.x4.trans.shared.b16 {%0,%1,%2,%3}, [%4];"
                 : "=r"(r[0]), "=r"(r[1]), "=r"(r[2]), "=r"(r[3]) : "r"(addr));
}
__device__ __forceinline__ void mma16816(float* c, const uint32_t* a, const uint32_t* b) {
    asm volatile(
        "mma.sync.aligned.m16n8k16.row.col.f32.bf16.bf16.f32 "
        "{%0,%1,%2,%3}, {%4,%5,%6,%7}, {%8,%9}, {%0,%1,%2,%3};"
        : "+f"(c[0]), "+f"(c[1]), "+f"(c[2]), "+f"(c[3])
        : "r"(a[0]), "r"(a[1]), "r"(a[2]), "r"(a[3]), "r"(b[0]), "r"(b[1]));
}
__device__ __forceinline__ void cpasync16(uint32_t dst, const void* src, int srcsize) {
    asm volatile("cp.async.cg.shared.global [%0], [%1], 16, %2;"
                 :: "r"(dst), "l"(src), "r"(srcsize) : "memory");
}
#define CP_COMMIT() asm volatile("cp.async.commit_group;" ::: "memory")
#define CP_WAIT1()  asm volatile("cp.async.wait_group 1;" ::: "memory")
#define CP_WAIT0()  asm volatile("cp.async.wait_group 0;" ::: "memory")

// ---------------------------------------------------------------------------
// Weight prep: pack + transpose + bf16-split (36 input-derived chunks).
// ---------------------------------------------------------------------------
__global__ void prep_w_kernel(const float* __restrict__ Wl, const float* __restrict__ Wr,
                              const float* __restrict__ pW1, const float* __restrict__ qW1) {
    int t = blockIdx.x * blockDim.x + threadIdx.x;
    if (t >= 36 * 4096) return;
    int cg = t >> 12;
    int within = t & 4095;
    int kl = within >> 7;      // 0..31
    int n  = within & 127;
    float v;
    if (cg < 24) {
        int g = cg >> 3, c = cg & 7;
        int kk = c * 32 + kl;
        v = (kk < 128) ? Wl[g * 16384 + kk * 128 + n]
                       : Wr[g * 16384 + (kk - 128) * 128 + n];
    } else if (cg < 28) {
        int kk = (cg - 24) * 32 + kl;
        v = pW1[kk * 128 + n];
    } else if (cg < 32) {
        int kk = (cg - 28) * 32 + kl;
        v = qW1[kk * 128 + n];
    } else {
        int kk = (cg - 32) * 32 + kl;
        v = qW1[(128 + kk) * 128 + n];
    }
    bf16 hi = __float2bfloat16(v);
    bf16 lo = __float2bfloat16(v - __bfloat162float(hi));
    g_wh[cg * 4096 + kl * 128 + n] = hi;
    g_wl[cg * 4096 + kl * 128 + n] = lo;
}

// ---------------------------------------------------------------------------
// Composite weights in fp32: W_U = pW2@qW1a (y=0), W_V = pW2@qW1b (y=1),
// written straight into weight-chunk layout (chunks 36-39 / 40-43).
// Grid (128, 2), 128 threads. ~2 MFMA total.
// ---------------------------------------------------------------------------
__global__ void composite_kernel(const float* __restrict__ pW2,
                                 const float* __restrict__ qW1) {
    __shared__ float row[128];
    int k = blockIdx.x, n = threadIdx.x;
    row[n] = pW2[k * 128 + n];
    __syncthreads();
    const float* Q = qW1 + (size_t)blockIdx.y * 128 * 128;
    float s = 0.f;
#pragma unroll 8
    for (int m = 0; m < 128; m++) s += row[m] * Q[m * 128 + n];
    bf16 hi = __float2bfloat16(s);
    bf16 lo = __float2bfloat16(s - __bfloat162float(hi));
    size_t off = (size_t)(36 + blockIdx.y * 4 + (k >> 5)) * 4096 +
                 (size_t)(k & 31) * 128 + n;
    g_wh[off] = hi;
    g_wl[off] = lo;
}

// ---------------------------------------------------------------------------
// Bias composition: cvec = qb1 + pb2@qW1a + pb2@qW1b  (1 block, 128 threads)
// ---------------------------------------------------------------------------
__global__ void cvec_kernel(const float* __restrict__ qW1,
                            const float* __restrict__ pb2,
                            const float* __restrict__ qb1) {
    int j = threadIdx.x;
    float c = qb1[j];
    for (int k = 0; k < 128; k++) {
        float p = pb2[k];
        c += p * (qW1[k * 128 + j] + qW1[(128 + k) * 128 + j]);
    }
    g_cvec[j] = c;
}

// ---------------------------------------------------------------------------
// Convert x (fp32) -> bf16 hi/lo pair (sel 0)
// ---------------------------------------------------------------------------
__global__ void convert_x_kernel(const float* __restrict__ x, int n32) {
    int i = blockIdx.x * blockDim.x + threadIdx.x;
    if (i >= n32) return;
    float4 v = ((const float4*)x)[i];
    bf16 h0 = __float2bfloat16(v.x), h1 = __float2bfloat16(v.y);
    bf16 h2 = __float2bfloat16(v.z), h3 = __float2bfloat16(v.w);
    bf16 l0 = __float2bfloat16(v.x - __bfloat162float(h0));
    bf16 l1 = __float2bfloat16(v.y - __bfloat162float(h1));
    bf16 l2 = __float2bfloat16(v.z - __bfloat162float(h2));
    bf16 l3 = __float2bfloat16(v.w - __bfloat162float(h3));
    __nv_bfloat162 hA = __halves2bfloat162(h0, h1), hB = __halves2bfloat162(h2, h3);
    __nv_bfloat162 lA = __halves2bfloat162(l0, l1), lB = __halves2bfloat162(l2, l3);
    ((uint2*)g_xh)[i] = make_uint2(*(uint32_t*)&hA, *(uint32_t*)&hB);
    ((uint2*)g_xl)[i] = make_uint2(*(uint32_t*)&lA, *(uint32_t*)&lB);
}

// ---------------------------------------------------------------------------
// Init / CSR build
// ---------------------------------------------------------------------------
__global__ void init_kernel(const unsigned int* __restrict__ eiw,
                            const unsigned int* __restrict__ piw, int n) {
    int i = blockIdx.x * blockDim.x + threadIdx.x;
    if (i < n) g_counts[i] = 0;
    if (blockIdx.x == 0) {
        unsigned ve = eiw[2 * threadIdx.x + 1];
        unsigned vp = piw[2 * threadIdx.x + 1];
        int e0 = __syncthreads_and(ve == 0u);
        int p0 = __syncthreads_and(vp == 0u);
        if (threadIdx.x == 0) { g_ei64 = e0; g_pi64 = p0; g_total = 0; }
    }
}

__global__ void count_kernel(const void* __restrict__ ei, int E) {
    int e = blockIdx.x * blockDim.x + threadIdx.x;
    if (e < E) atomicAdd(&g_counts[getidx(ei, (long long)E + e, g_ei64)], 1);
}

__global__ void segment_kernel(int n) {
    __shared__ int wsum[8];
    __shared__ int blockbase;
    int i = blockIdx.x * 256 + threadIdx.x;
    int lane = threadIdx.x & 31;
    int wid  = threadIdx.x >> 5;
    int c = (i < n) ? g_counts[i] : 0;
    int s = c;
#pragma unroll
    for (int off = 1; off < 32; off <<= 1) {
        int v = __shfl_up_sync(0xFFFFFFFFu, s, off);
        if (lane >= off) s += v;
    }
    if (lane == 31) wsum[wid] = s;
    __syncthreads();
    if (wid == 0) {
        int v = (lane < 8) ? wsum[lane] : 0;
#pragma unroll
        for (int off = 1; off < 8; off <<= 1) {
            int t2 = __shfl_up_sync(0xFFFFFFFFu, v, off);
            if (lane >= off) v += t2;
        }
        if (lane < 8) wsum[lane] = v;
        int total = __shfl_sync(0xFFFFFFFFu, v, 7);
        if (lane == 0) blockbase = atomicAdd(&g_total, total);
    }
    __syncthreads();
    if (i < n) {
        int excl = blockbase + (wid > 0 ? wsum[wid - 1] : 0) + s - c;
        g_offsets[i] = excl;
        g_cursor[i]  = excl;
        g_invdeg[i]  = 1.0f / (float)max(c, 1);
    }
}

__global__ void fill_kernel(const void* __restrict__ ei, int E) {
    int e = blockIdx.x * blockDim.x + threadIdx.x;
    if (e < E) {
        int s = getidx(ei, e, g_ei64);
        int d = getidx(ei, (long long)E + e, g_ei64);
        g_csr[atomicAdd(&g_cursor[d], 1)] = s;
    }
}

// ---------------------------------------------------------------------------
// Mean aggregation over bf16 pairs -> ag bf16 pair. One warp/node.
// ---------------------------------------------------------------------------
__global__ void aggr_kernel(int xsel, int n) {
    int w = (blockIdx.x * blockDim.x + threadIdx.x) >> 5;
    int lane = threadIdx.x & 31;
    if (w >= n) return;
    const bf16* xh = pair_h(xsel);
    const bf16* xl = pair_l(xsel);
    int beg = g_offsets[w];
    int cnt = g_counts[w];
    float a0 = 0.f, a1 = 0.f, a2 = 0.f, a3 = 0.f;
    for (int j = beg; j < beg + cnt; ++j) {
        int s = g_csr[j];
        uint2 uh = *(const uint2*)(xh + s * 128 + lane * 4);
        uint2 ul = *(const uint2*)(xl + s * 128 + lane * 4);
        __nv_bfloat162 h01 = *(__nv_bfloat162*)&uh.x;
        __nv_bfloat162 h23 = *(__nv_bfloat162*)&uh.y;
        __nv_bfloat162 l01 = *(__nv_bfloat162*)&ul.x;
        __nv_bfloat162 l23 = *(__nv_bfloat162*)&ul.y;
        a0 += __low2float(h01)  + __low2float(l01);
        a1 += __high2float(h01) + __high2float(l01);
        a2 += __low2float(h23)  + __low2float(l23);
        a3 += __high2float(h23) + __high2float(l23);
    }
    float inv = g_invdeg[w];
    a0 *= inv; a1 *= inv; a2 *= inv; a3 *= inv;
    bf16 h0 = __float2bfloat16(a0), h1 = __float2bfloat16(a1);
    bf16 h2 = __float2bfloat16(a2), h3 = __float2bfloat16(a3);
    bf16 l0 = __float2bfloat16(a0 - __bfloat162float(h0));
    bf16 l1 = __float2bfloat16(a1 - __bfloat162float(h1));
    bf16 l2 = __float2bfloat16(a2 - __bfloat162float(h2));
    bf16 l3 = __float2bfloat16(a3 - __bfloat162float(h3));
    __nv_bfloat162 hA = __halves2bfloat162(h0, h1), hB = __halves2bfloat162(h2, h3);
    __nv_bfloat162 lA = __halves2bfloat162(l0, l1), lB = __halves2bfloat162(l2, l3);
    *(uint2*)(g_agh + w * 128 + lane * 4) = make_uint2(*(uint32_t*)&hA, *(uint32_t*)&hB);
    *(uint2*)(g_agl + w * 128 + lane * 4) = make_uint2(*(uint32_t*)&lA, *(uint32_t*)&lB);
}

// ---------------------------------------------------------------------------
// Tensor-core GEMM via mma.sync (bf16 3-term split, fp32 accum).
// cp.async double-buffered. Block 128x128, 8 warps, warp tile 32x64.
// __launch_bounds__(256, 2): cap 128 regs -> 2 CTAs/SM for latency hiding.
// ---------------------------------------------------------------------------
constexpr int A_ST = 40;
constexpr int W_ST = 136;
constexpr int A_BUF = 128 * A_ST;
constexpr int W_BUF = 32 * W_ST;
constexpr int SBUF  = 2 * A_BUF + 2 * W_BUF;
constexpr int GEMM_SMEM_BYTES = 2 * SBUF * 2;     // 75776 bytes

__global__ void __launch_bounds__(256, 2)
gemm_mma(int a1sel, int a2sel, int wbase0, int wbase1,
         const float* __restrict__ bias, int relu, int outmode,
         int outsel0, int outsel1, int M) {
    extern __shared__ __align__(16) bf16 dyn[];

    const int wbase  = (blockIdx.y == 0) ? wbase0 : wbase1;
    const int outsel = (blockIdx.y == 0) ? outsel0 : outsel1;

    const int tid = threadIdx.x;
    const int wid = tid >> 5;
    const int lane = tid & 31;
    const int wr = wid >> 1;
    const int wc = wid & 1;
    const int m0 = blockIdx.x * 128;
    const int lrow = lane & 15;
    const int lhalf = lane >> 4;

    const uint32_t dynb = smem_u32(dyn);
    const uint32_t bAh0 = dynb;
    const uint32_t bAl0 = dynb + A_BUF * 2;
    const uint32_t bWh0 = dynb + 2 * A_BUF * 2;
    const uint32_t bWl0 = dynb + (2 * A_BUF + W_BUF) * 2;
    const uint32_t bstep = SBUF * 2;

    const int nch = (a2sel < 0) ? 4 : 8;

    const int ar0 = tid >> 2, aq0 = (tid & 3) * 8;
    const int ar1 = (tid + 256) >> 2, aq1 = aq0;
    const int wr0 = tid >> 4, wq0 = (tid & 15) * 8;
    const int wr1 = (tid + 256) >> 4, wq1 = wq0;

    auto stage = [&](int cc, int b) {
        const int half = (nch == 8 && cc >= 4) ? 1 : 0;
        const int psel = half ? a2sel : a1sel;
        const bf16* Ah = pair_h(psel);
        const bf16* Al = pair_l(psel);
        const int kbase = (cc & 3) * 32;
        const bf16* wh = g_wh + (size_t)(wbase + cc) * 4096;
        const bf16* wl = g_wl + (size_t)(wbase + cc) * 4096;
        uint32_t base = (uint32_t)b * bstep;

        int gr0 = m0 + ar0, gr1 = m0 + ar1;
        int sz0 = (gr0 < M) ? 16 : 0;
        int sz1 = (gr1 < M) ? 16 : 0;
        int cg0 = min(gr0, M - 1), cg1 = min(gr1, M - 1);
        uint32_t d0 = (uint32_t)((ar0 * A_ST + aq0) * 2);
        uint32_t d1 = (uint32_t)((ar1 * A_ST + aq1) * 2);
        cpasync16(bAh0 + base + d0, Ah + (size_t)cg0 * 128 + kbase + aq0, sz0);
        cpasync16(bAh0 + base + d1, Ah + (size_t)cg1 * 128 + kbase + aq1, sz1);
        cpasync16(bAl0 + base + d0, Al + (size_t)cg0 * 128 + kbase + aq0, sz0);
        cpasync16(bAl0 + base + d1, Al + (size_t)cg1 * 128 + kbase + aq1, sz1);
        uint32_t e0 = (uint32_t)((wr0 * W_ST + wq0) * 2);
        uint32_t e1 = (uint32_t)((wr1 * W_ST + wq1) * 2);
        cpasync16(bWh0 + base + e0, wh + wr0 * 128 + wq0, 16);
        cpasync16(bWh0 + base + e1, wh + wr1 * 128 + wq1, 16);
        cpasync16(bWl0 + base + e0, wl + wr0 * 128 + wq0, 16);
        cpasync16(bWl0 + base + e1, wl + wr1 * 128 + wq1, 16);
    };

    float acc[2][8][4];
#pragma unroll
    for (int i = 0; i < 2; i++)
#pragma unroll
        for (int j = 0; j < 8; j++)
#pragma unroll
            for (int k = 0; k < 4; k++) acc[i][j][k] = 0.f;

    stage(0, 0);
    CP_COMMIT();

    for (int c = 0; c < nch; c++) {
        const int cb = c & 1;
        if (c + 1 < nch) {
            stage(c + 1, cb ^ 1);
            CP_COMMIT();
            CP_WAIT1();
        } else {
            CP_WAIT0();
        }
        __syncthreads();

        const uint32_t base = (uint32_t)cb * bstep;
        const uint32_t aH = bAh0 + base, aL = bAl0 + base;
        const uint32_t wH = bWh0 + base, wL = bWl0 + base;
#pragma unroll
        for (int ks = 0; ks < 2; ks++) {
            uint32_t fH[2][4], fL[2][4];
#pragma unroll
            for (int mt = 0; mt < 2; mt++) {
                uint32_t off = (uint32_t)(((32 * wr + 16 * mt + lrow) * A_ST +
                                           ks * 16 + 8 * lhalf) * 2);
                ldmx4(fH[mt], aH + off);
                ldmx4(fL[mt], aL + off);
            }
#pragma unroll
            for (int ng = 0; ng < 4; ng++) {
                uint32_t bH[4], bL[4];
                uint32_t off = (uint32_t)(((ks * 16 + lrow) * W_ST +
                                           64 * wc + 16 * ng + 8 * lhalf) * 2);
                ldmx4t(bH, wH + off);
                ldmx4t(bL, wL + off);
#pragma unroll
                for (int mt = 0; mt < 2; mt++) {
                    mma16816(acc[mt][2 * ng],     fH[mt], bH);
                    mma16816(acc[mt][2 * ng],     fH[mt], bL);
                    mma16816(acc[mt][2 * ng],     fL[mt], bH);
                    mma16816(acc[mt][2 * ng + 1], fH[mt], bH + 2);
                    mma16816(acc[mt][2 * ng + 1], fH[mt], bL + 2);
                    mma16816(acc[mt][2 * ng + 1], fL[mt], bH + 2);
                }
            }
        }
        __syncthreads();
    }

    // Epilogue
    float* Cf = (outmode == 1) ? ((outsel == 0) ? g_b0 : g_b1) : nullptr;
    bf16* oh = (outmode == 0) ? (bf16*)pair_h(outsel) : nullptr;
    bf16* ol = (outmode == 0) ? (bf16*)pair_l(outsel) : nullptr;

#pragma unroll
    for (int mt = 0; mt < 2; mt++) {
#pragma unroll
        for (int nt = 0; nt < 8; nt++) {
            int col = 64 * wc + 8 * nt + 2 * (lane & 3);
            float bb0 = bias ? bias[col] : 0.f;
            float bb1 = bias ? bias[col + 1] : 0.f;
#pragma unroll
            for (int h = 0; h < 2; h++) {
                int r = m0 + 32 * wr + 16 * mt + (lane >> 2) + 8 * h;
                if (r < M) {
                    float v0 = acc[mt][nt][2 * h]     + bb0;
                    float v1 = acc[mt][nt][2 * h + 1] + bb1;
                    if (relu) { v0 = fmaxf(v0, 0.f); v1 = fmaxf(v1, 0.f); }
                    if (outmode == 1) {
                        *(float2*)(Cf + (size_t)r * 128 + col) = make_float2(v0, v1);
                    } else {
                        bf16 h0 = __float2bfloat16(v0);
                        bf16 h1 = __float2bfloat16(v1);
                        bf16 l0 = __float2bfloat16(v0 - __bfloat162float(h0));
                        bf16 l1 = __float2bfloat16(v1 - __bfloat162float(h1));
                        __nv_bfloat162 hp = __halves2bfloat162(h0, h1);
                        __nv_bfloat162 lp = __halves2bfloat162(l0, l1);
                        *(uint32_t*)(oh + (size_t)r * 128 + col) = *(uint32_t*)&hp;
                        *(uint32_t*)(ol + (size_t)r * 128 + col) = *(uint32_t*)&lp;
                    }
                }
            }
        }
    }
}

// ---------------------------------------------------------------------------
// Edge predict: y[e] = relu(U[i] + V[j] + cvec) . qW2 + qb2  (one warp/edge)
// ---------------------------------------------------------------------------
__global__ void predict_kernel(const void* __restrict__ pidx,
                               const float* __restrict__ qW2,
                               const float* __restrict__ qb2,
                               float* __restrict__ y, int EP) {
    int w = (blockIdx.x * blockDim.x + threadIdx.x) >> 5;
    int lane = threadIdx.x & 31;
    if (w >= EP) return;
    int is64 = g_pi64;
    int i = getidx(pidx, w, is64);
    int j = getidx(pidx, (long long)EP + w, is64);
    float4 u = ((const float4*)g_b0)[i * 32 + lane];
    float4 v = ((const float4*)g_b1)[j * 32 + lane];
    float4 b = ((const float4*)g_cvec)[lane];
    float4 q = ((const float4*)qW2)[lane];
    float h0 = fmaxf(u.x + v.x + b.x, 0.f);
    float h1 = fmaxf(u.y + v.y + b.y, 0.f);
    float h2 = fmaxf(u.z + v.z + b.z, 0.f);
    float h3 = fmaxf(u.w + v.w + b.w, 0.f);
    float p = h0 * q.x + h1 * q.y + h2 * q.z + h3 * q.w;
#pragma unroll
    for (int o = 16; o > 0; o >>= 1) p += __shfl_xor_sync(0xFFFFFFFFu, p, o);
    if (lane == 0) y[w] = p + qb2[0];
}

// ---------------------------------------------------------------------------
// Launch
// ---------------------------------------------------------------------------
extern "C" void kernel_launch(void* const* d_in, const int* in_sizes, int n_in,
                              void* d_out, int out_size) {
    const float* x   = (const float*)d_in[0];
    const void*  ei  = d_in[2];
    const void*  pi  = d_in[3];
    const float* Wl  = (const float*)d_in[4];
    const float* bl  = (const float*)d_in[5];
    const float* Wr  = (const float*)d_in[6];
    // d_in[7..10]: edge-update MLP params — dead code w.r.t. the output
    const float* pW1 = (const float*)d_in[11];
    const float* pb1 = (const float*)d_in[12];
    const float* pW2 = (const float*)d_in[13];
    const float* pb2 = (const float*)d_in[14];
    const float* qW1 = (const float*)d_in[15];
    const float* qb1 = (const float*)d_in[16];
    const float* qW2 = (const float*)d_in[17];
    const float* qb2 = (const float*)d_in[18];

    const int N  = in_sizes[0] / 128;
    const int E  = in_sizes[2] / 2;
    const int EP = in_sizes[3] / 2;
    const int L  = in_sizes[4] / (128 * 128);

    cudaFuncSetAttribute(gemm_mma, cudaFuncAttributeMaxDynamicSharedMemorySize,
                         GEMM_SMEM_BYTES);

    // Weight pack + composites + x conversion (independent of CSR)
    prep_w_kernel<<<(36 * 4096 + 255) / 256, 256>>>(Wl, Wr, pW1, qW1);
    composite_kernel<<<dim3(128, 2), 128>>>(pW2, qW1);
    cvec_kernel<<<1, 128>>>(qW1, pb2, qb1);
    convert_x_kernel<<<(N * 32 + 255) / 256, 256>>>(x, N * 32);

    // CSR build
    init_kernel<<<(N + 255) / 256, 256>>>((const unsigned int*)ei,
                                          (const unsigned int*)pi, N);
    count_kernel<<<(E + 255) / 256, 256>>>(ei, E);
    segment_kernel<<<(N + 255) / 256, 256>>>(N);
    fill_kernel<<<(E + 255) / 256, 256>>>(ei, E);

    const int gemm_blocks = (N + 127) / 128;
    const int aggr_blocks = (N * 32 + 255) / 256;

    // GNN layers: cur pair sel 0(x) -> 1 -> 2 -> 1
    int cur = 0;
    for (int l = 0; l < L; l++) {
        int nxt = (l == 0) ? 1 : (l == 1) ? 2 : 1;
        aggr_kernel<<<aggr_blocks, 256>>>(cur, N);
        gemm_mma<<<dim3(gemm_blocks, 1), 256, GEMM_SMEM_BYTES>>>(
            3, cur, l * 8, 0, bl + l * 128, 1, 0, nxt, 0, N);
        cur = nxt;
    }
    // cur = 1. Post MLP first half: z = relu(p0@pW1 + pb1) -> sel 2
    gemm_mma<<<dim3(gemm_blocks, 1), 256, GEMM_SMEM_BYTES>>>(
        1, -1, 24, 0, pb1, 1, 0, 2, 0, N);
    // U/V from z with composite weights: y=0 -> W_U -> g_b0 ; y=1 -> W_V -> g_b1
    gemm_mma<<<dim3(gemm_blocks, 2), 256, GEMM_SMEM_BYTES>>>(
        2, -1, 36, 40, nullptr, 0, 1, 0, 1, N);

    predict_kernel<<<(EP * 32 + 255) / 256, 256>>>(pi, qW2, qb2, (float*)d_out, EP);
}